// round 1
// baseline (speedup 1.0000x reference)
#include <cuda_runtime.h>
#include <cuda_bf16.h>
#include <math.h>

// Problem constants
#define BB 2
#define SS 2048
#define DD 1024
#define HH 16
#define DKK 64
#define DFFN 4096
#define NTOK (BB*SS)          // 4096
#define LN_EPS 1e-6f

// ---------------------------------------------------------------------------
// Scratch buffers (static __device__ arrays: allocation-guard-safe)
// ---------------------------------------------------------------------------
__device__ float g_xn [ (size_t)NTOK * DD ];
__device__ float g_q  [ (size_t)NTOK * DD ];
__device__ float g_k2 [ (size_t)NTOK * DD ];
__device__ float g_v2 [ (size_t)NTOK * DD ];
__device__ float g_av [ (size_t)NTOK * DD ];
__device__ float g_x1 [ (size_t)NTOK * DD ];
__device__ float g_xn2[ (size_t)NTOK * DD ];
__device__ float g_h  [ (size_t)NTOK * DFFN ];

// ---------------------------------------------------------------------------
// Reductions
// ---------------------------------------------------------------------------
__device__ __forceinline__ float warpReduceSum(float v) {
    #pragma unroll
    for (int o = 16; o > 0; o >>= 1) v += __shfl_xor_sync(0xffffffffu, v, o);
    return v;
}
__device__ __forceinline__ float warpReduceMax(float v) {
    #pragma unroll
    for (int o = 16; o > 0; o >>= 1) v = fmaxf(v, __shfl_xor_sync(0xffffffffu, v, o));
    return v;
}

// ---------------------------------------------------------------------------
// LayerNorm: one block (256 threads) per row of 1024.
// torch semantics: alpha * (x - mean) / (sqrt(var_unbiased) + eps) + bias
// ---------------------------------------------------------------------------
__global__ __launch_bounds__(256) void layernorm_k(
    const float* __restrict__ x, const float* __restrict__ alpha,
    const float* __restrict__ beta, float* __restrict__ out)
{
    int row = blockIdx.x;
    const float* xr = x + (size_t)row * DD;
    int i = threadIdx.x * 4;                 // 256*4 = 1024
    float4 xv = *(const float4*)(xr + i);
    float s  = xv.x + xv.y + xv.z + xv.w;
    float s2 = xv.x*xv.x + xv.y*xv.y + xv.z*xv.z + xv.w*xv.w;

    __shared__ float rs[8], rs2[8];
    __shared__ float smean, sinv;
    s  = warpReduceSum(s);
    s2 = warpReduceSum(s2);
    int w = threadIdx.x >> 5, l = threadIdx.x & 31;
    if (l == 0) { rs[w] = s; rs2[w] = s2; }
    __syncthreads();
    if (threadIdx.x == 0) {
        float S = 0.f, S2 = 0.f;
        #pragma unroll
        for (int k = 0; k < 8; k++) { S += rs[k]; S2 += rs2[k]; }
        float mean = S * (1.0f / (float)DD);
        float var  = (S2 - (float)DD * mean * mean) * (1.0f / (float)(DD - 1));
        var = fmaxf(var, 0.0f);
        smean = mean;
        sinv  = 1.0f / (sqrtf(var) + LN_EPS);
    }
    __syncthreads();
    float m = smean, inv = sinv;
    float4 av = *(const float4*)(alpha + i);
    float4 bv = *(const float4*)(beta  + i);
    float4 o;
    o.x = av.x * (xv.x - m) * inv + bv.x;
    o.y = av.y * (xv.y - m) * inv + bv.y;
    o.z = av.z * (xv.z - m) * inv + bv.z;
    o.w = av.w * (xv.w - m) * inv + bv.w;
    *(float4*)(out + (size_t)row * DD + i) = o;
}

// ---------------------------------------------------------------------------
// NT GEMM: C[M,N] = A[M,K] @ B[N,K]^T  (+bias[col]) (ReLU) (+res[row,col])
// 128x128 block tile, BK=16, 256 threads, 8x8 per thread.
// All of M,N,K divisible by tile sizes for this problem.
// ---------------------------------------------------------------------------
template<bool BIAS, bool RELU, bool RES>
__global__ __launch_bounds__(256) void gemm_nt(
    const float* __restrict__ A, const float* __restrict__ B,
    const float* __restrict__ bias, const float* __restrict__ res,
    float* __restrict__ C, int M, int N, int K)
{
    __shared__ float As[16][132];
    __shared__ float Bs[16][132];
    int bx = blockIdx.x, by = blockIdx.y;
    int t = threadIdx.x;
    int tx = t & 15, ty = t >> 4;
    int aRow0 = by * 128, bRow0 = bx * 128;
    int lr = t >> 2;          // 0..63
    int lc = (t & 3) * 4;     // 0,4,8,12

    float acc[8][8];
    #pragma unroll
    for (int i = 0; i < 8; i++)
        #pragma unroll
        for (int j = 0; j < 8; j++) acc[i][j] = 0.f;

    for (int k0 = 0; k0 < K; k0 += 16) {
        #pragma unroll
        for (int i = 0; i < 2; i++) {
            int r = lr + i * 64;
            float4 va = *(const float4*)(A + (size_t)(aRow0 + r) * K + k0 + lc);
            As[lc+0][r] = va.x; As[lc+1][r] = va.y; As[lc+2][r] = va.z; As[lc+3][r] = va.w;
            float4 vb = *(const float4*)(B + (size_t)(bRow0 + r) * K + k0 + lc);
            Bs[lc+0][r] = vb.x; Bs[lc+1][r] = vb.y; Bs[lc+2][r] = vb.z; Bs[lc+3][r] = vb.w;
        }
        __syncthreads();
        #pragma unroll
        for (int kk = 0; kk < 16; kk++) {
            float ra[8], rb[8];
            #pragma unroll
            for (int i = 0; i < 8; i++) ra[i] = As[kk][ty * 8 + i];
            #pragma unroll
            for (int j = 0; j < 8; j++) rb[j] = Bs[kk][tx * 8 + j];
            #pragma unroll
            for (int i = 0; i < 8; i++)
                #pragma unroll
                for (int j = 0; j < 8; j++)
                    acc[i][j] = fmaf(ra[i], rb[j], acc[i][j]);
        }
        __syncthreads();
    }

    #pragma unroll
    for (int i = 0; i < 8; i++) {
        int row = aRow0 + ty * 8 + i;
        #pragma unroll
        for (int j = 0; j < 8; j++) {
            int col = bRow0 + tx * 8 + j;
            float v = acc[i][j];
            if (BIAS) v += bias[col];
            if (RELU) v = fmaxf(v, 0.f);
            if (RES)  v += res[(size_t)row * N + col];
            C[(size_t)row * N + col] = v;
        }
    }
}

// ---------------------------------------------------------------------------
// Attention: one block per (b, h, 16-query tile). 256 threads.
// Two-pass softmax with full score tile resident in dynamic smem.
// q,k,v laid out as [token, D] with head h at cols h*64..h*64+63.
// ---------------------------------------------------------------------------
#define QT 16
#define ATTN_SMEM_FLOATS (QT*SS + QT*64 + 4*QT*64 + QT)
#define ATTN_SMEM_BYTES  (ATTN_SMEM_FLOATS * 4)

__global__ __launch_bounds__(256) void attn_k(
    const float* __restrict__ q, const float* __restrict__ k,
    const float* __restrict__ v, const int* __restrict__ mask,
    float* __restrict__ av)
{
    extern __shared__ float sm[];
    float* sc   = sm;                       // QT*2048
    float* qs   = sc + QT * SS;             // QT*64
    float* part = qs + QT * 64;             // 4*QT*64
    float* rinv = part + 4 * QT * 64;       // QT

    int t   = threadIdx.x;
    int blk = blockIdx.x;
    int qt  = blk & 127;                    // 2048/16 tiles
    int bh  = blk >> 7;
    int h   = bh & (HH - 1), b = bh >> 4;
    int q0  = qt * QT;
    size_t base = (size_t)b * SS * DD + (size_t)h * DKK;

    // load Q tile (16x64) into smem
    {
        int r = t >> 4;               // 0..15
        int c = (t & 15) * 4;         // 0..60
        *(float4*)(qs + r * 64 + c) =
            *(const float4*)(q + base + (size_t)(q0 + r) * DD + c);
    }
    __syncthreads();

    // scores: each thread handles 8 key rows (strided), 16 queries each
    const int* mk = mask + b * SS;
    for (int j = t; j < SS; j += 256) {
        const float* kr = k + base + (size_t)j * DD;
        float acc[QT];
        #pragma unroll
        for (int r = 0; r < QT; r++) acc[r] = 0.f;
        #pragma unroll
        for (int c = 0; c < DKK; c += 4) {
            float4 kv = *(const float4*)(kr + c);
            #pragma unroll
            for (int r = 0; r < QT; r++) {
                const float* qr = qs + r * 64 + c;
                acc[r] += qr[0]*kv.x + qr[1]*kv.y + qr[2]*kv.z + qr[3]*kv.w;
            }
        }
        bool dead = (mk[j] == 0);
        #pragma unroll
        for (int r = 0; r < QT; r++)
            sc[r * SS + j] = dead ? -1e9f : acc[r] * 0.125f;   // 1/sqrt(64)
    }
    __syncthreads();

    // softmax per row: 8 warps, 2 rows each
    int w = t >> 5, l = t & 31;
    for (int r = w; r < QT; r += 8) {
        float* s = sc + r * SS;
        float m = -1e30f;
        for (int j = l; j < SS; j += 32) m = fmaxf(m, s[j]);
        m = warpReduceMax(m);
        float sum = 0.f;
        for (int j = l; j < SS; j += 32) {
            float e = __expf(s[j] - m);
            s[j] = e;
            sum += e;
        }
        sum = warpReduceSum(sum);
        if (l == 0) rinv[r] = 1.0f / sum;
    }
    __syncthreads();

    // AV: group g = t/64 handles keys [g*512, g*512+512), lane d = t%64
    int d = t & 63, g = t >> 6;
    const float* vp = v + base + d;
    float acc[QT];
    #pragma unroll
    for (int r = 0; r < QT; r++) acc[r] = 0.f;
    for (int j0 = g * 512; j0 < g * 512 + 512; j0 += 4) {
        float v0 = vp[(size_t)(j0+0) * DD];
        float v1 = vp[(size_t)(j0+1) * DD];
        float v2 = vp[(size_t)(j0+2) * DD];
        float v3 = vp[(size_t)(j0+3) * DD];
        #pragma unroll
        for (int r = 0; r < QT; r++) {
            float4 s4 = *(const float4*)(sc + r * SS + j0);
            acc[r] += s4.x*v0 + s4.y*v1 + s4.z*v2 + s4.w*v3;
        }
    }
    #pragma unroll
    for (int r = 0; r < QT; r++) part[(g * QT + r) * 64 + d] = acc[r];
    __syncthreads();

    // combine 4 partials and write out
    for (int idx = t; idx < QT * 64; idx += 256) {
        int r = idx >> 6, dd = idx & 63;
        float s = part[r * 64 + dd] + part[(QT + r) * 64 + dd]
                + part[(2*QT + r) * 64 + dd] + part[(3*QT + r) * 64 + dd];
        av[base + (size_t)(q0 + r) * DD + dd] = s * rinv[r];
    }
}

// ---------------------------------------------------------------------------
// Driver
// ---------------------------------------------------------------------------
extern "C" void kernel_launch(void* const* d_in, const int* in_sizes, int n_in,
                              void* d_out, int out_size)
{
    const float* x      = (const float*)d_in[0];
    const int*   mask   = (const int*)  d_in[1];
    const float* wq     = (const float*)d_in[2];
    const float* wk     = (const float*)d_in[3];
    const float* wv     = (const float*)d_in[4];
    const float* wo     = (const float*)d_in[5];
    const float* w1     = (const float*)d_in[6];
    const float* b1     = (const float*)d_in[7];
    const float* w2     = (const float*)d_in[8];
    const float* b2     = (const float*)d_in[9];
    const float* alpha1 = (const float*)d_in[10];
    const float* bias1  = (const float*)d_in[11];
    const float* alpha2 = (const float*)d_in[12];
    const float* bias2  = (const float*)d_in[13];
    float* out = (float*)d_out;

    float *xn, *qb, *kb, *vb, *avb, *x1, *xn2, *hb;
    cudaGetSymbolAddress((void**)&xn,  g_xn);
    cudaGetSymbolAddress((void**)&qb,  g_q);
    cudaGetSymbolAddress((void**)&kb,  g_k2);
    cudaGetSymbolAddress((void**)&vb,  g_v2);
    cudaGetSymbolAddress((void**)&avb, g_av);
    cudaGetSymbolAddress((void**)&x1,  g_x1);
    cudaGetSymbolAddress((void**)&xn2, g_xn2);
    cudaGetSymbolAddress((void**)&hb,  g_h);

    cudaFuncSetAttribute(attn_k, cudaFuncAttributeMaxDynamicSharedMemorySize,
                         ATTN_SMEM_BYTES);

    // 1. LN1
    layernorm_k<<<NTOK, 256>>>(x, alpha1, bias1, xn);

    // 2-4. Q, K, V projections
    dim3 gProj(DD / 128, NTOK / 128);       // (8, 32)
    gemm_nt<false,false,false><<<gProj, 256>>>(xn, wq, nullptr, nullptr, qb, NTOK, DD, DD);
    gemm_nt<false,false,false><<<gProj, 256>>>(xn, wk, nullptr, nullptr, kb, NTOK, DD, DD);
    gemm_nt<false,false,false><<<gProj, 256>>>(xn, wv, nullptr, nullptr, vb, NTOK, DD, DD);

    // 5. attention
    attn_k<<<BB * HH * (SS / QT), 256, ATTN_SMEM_BYTES>>>(qb, kb, vb, mask, avb);

    // 6. output projection + residual
    gemm_nt<false,false,true><<<gProj, 256>>>(avb, wo, nullptr, x, x1, NTOK, DD, DD);

    // 7. LN2
    layernorm_k<<<NTOK, 256>>>(x1, alpha2, bias2, xn2);

    // 8. FFN up + bias + ReLU
    dim3 gF1(DFFN / 128, NTOK / 128);       // (32, 32)
    gemm_nt<true,true,false><<<gF1, 256>>>(xn2, w1, b1, nullptr, hb, NTOK, DFFN, DD);

    // 9. FFN down + bias + residual -> final output
    gemm_nt<true,false,true><<<gProj, 256>>>(hb, w2, b2, x1, out, NTOK, DD, DFFN);
}

// round 3
// speedup vs baseline: 1.8008x; 1.8008x over previous
#include <cuda_runtime.h>
#include <cuda_bf16.h>
#include <math.h>
#include <stdint.h>

// Problem constants
#define BB 2
#define SS 2048
#define DD 1024
#define HH 16
#define DKK 64
#define DFFN 4096
#define NTOK (BB*SS)          // 4096
#define LN_EPS 1e-6f

typedef __nv_bfloat16 bf16;

// ---------------------------------------------------------------------------
// Scratch (static __device__ arrays: allocation-guard-safe)
// ---------------------------------------------------------------------------
__device__ bf16  g_xnh [(size_t)NTOK*DD],  g_xnl [(size_t)NTOK*DD];
__device__ float g_q   [(size_t)NTOK*DD];
__device__ float g_kk  [(size_t)NTOK*DD];
__device__ float g_vv  [(size_t)NTOK*DD];
__device__ bf16  g_avh [(size_t)NTOK*DD],  g_avl [(size_t)NTOK*DD];
__device__ float g_x1  [(size_t)NTOK*DD];
__device__ bf16  g_xn2h[(size_t)NTOK*DD],  g_xn2l[(size_t)NTOK*DD];
__device__ bf16  g_hbh [(size_t)NTOK*DFFN], g_hbl[(size_t)NTOK*DFFN];
__device__ bf16  g_wqh [(size_t)DD*DD],   g_wql [(size_t)DD*DD];
__device__ bf16  g_wkh [(size_t)DD*DD],   g_wkl [(size_t)DD*DD];
__device__ bf16  g_wvh [(size_t)DD*DD],   g_wvl [(size_t)DD*DD];
__device__ bf16  g_woh [(size_t)DD*DD],   g_wol [(size_t)DD*DD];
__device__ bf16  g_w1h [(size_t)DFFN*DD], g_w1l [(size_t)DFFN*DD];
__device__ bf16  g_w2h [(size_t)DD*DFFN], g_w2l [(size_t)DD*DFFN];

// ---------------------------------------------------------------------------
// PTX helpers (cp.async + mma.sync)
// ---------------------------------------------------------------------------
__device__ __forceinline__ uint32_t smem_u32(const void* p) {
    uint32_t a;
    asm("{ .reg .u64 t; cvta.to.shared.u64 t, %1; cvt.u32.u64 %0, t; }"
        : "=r"(a) : "l"(p));
    return a;
}
__device__ __forceinline__ void cp16(uint32_t d, const void* s) {
    asm volatile("cp.async.cg.shared.global [%0], [%1], 16;\n" :: "r"(d), "l"(s));
}
__device__ __forceinline__ void cp_commit() { asm volatile("cp.async.commit_group;\n" ::); }
template<int N> __device__ __forceinline__ void cp_wait() {
    asm volatile("cp.async.wait_group %0;\n" :: "n"(N));
}

__device__ __forceinline__ void mma16816(float* c, const uint32_t* a, const uint32_t* b) {
    asm volatile(
        "mma.sync.aligned.m16n8k16.row.col.f32.bf16.bf16.f32 "
        "{%0,%1,%2,%3}, {%4,%5,%6,%7}, {%8,%9}, {%0,%1,%2,%3};"
        : "+f"(c[0]), "+f"(c[1]), "+f"(c[2]), "+f"(c[3])
        : "r"(a[0]), "r"(a[1]), "r"(a[2]), "r"(a[3]), "r"(b[0]), "r"(b[1]));
}

// ---------------------------------------------------------------------------
// Reductions
// ---------------------------------------------------------------------------
__device__ __forceinline__ float warpReduceSum(float v) {
    #pragma unroll
    for (int o = 16; o > 0; o >>= 1) v += __shfl_xor_sync(0xffffffffu, v, o);
    return v;
}
__device__ __forceinline__ float warpReduceMax(float v) {
    #pragma unroll
    for (int o = 16; o > 0; o >>= 1) v = fmaxf(v, __shfl_xor_sync(0xffffffffu, v, o));
    return v;
}

// ---------------------------------------------------------------------------
// Split fp32 -> bf16 (hi, lo). n4 = n/4.
// ---------------------------------------------------------------------------
__global__ __launch_bounds__(256) void split_k(
    const float* __restrict__ w, bf16* __restrict__ hi,
    bf16* __restrict__ lo, int n4)
{
    int i = blockIdx.x * 256 + threadIdx.x;
    if (i >= n4) return;
    float4 v = ((const float4*)w)[i];
    bf16 h0 = __float2bfloat16(v.x), h1 = __float2bfloat16(v.y);
    bf16 h2 = __float2bfloat16(v.z), h3 = __float2bfloat16(v.w);
    bf16 l0 = __float2bfloat16(v.x - __bfloat162float(h0));
    bf16 l1 = __float2bfloat16(v.y - __bfloat162float(h1));
    bf16 l2 = __float2bfloat16(v.z - __bfloat162float(h2));
    bf16 l3 = __float2bfloat16(v.w - __bfloat162float(h3));
    __nv_bfloat162* hp = (__nv_bfloat162*)hi;
    __nv_bfloat162* lp = (__nv_bfloat162*)lo;
    hp[i*2]   = __nv_bfloat162(h0, h1);
    hp[i*2+1] = __nv_bfloat162(h2, h3);
    lp[i*2]   = __nv_bfloat162(l0, l1);
    lp[i*2+1] = __nv_bfloat162(l2, l3);
}

// ---------------------------------------------------------------------------
// LayerNorm -> bf16 (hi, lo) pair. One 256-thread block per row of 1024.
// torch semantics: alpha * (x - mean) / (sqrt(var_unbiased) + eps) + bias
// ---------------------------------------------------------------------------
__global__ __launch_bounds__(256) void layernorm_k(
    const float* __restrict__ x, const float* __restrict__ alpha,
    const float* __restrict__ beta,
    bf16* __restrict__ oh, bf16* __restrict__ ol)
{
    int row = blockIdx.x;
    const float* xr = x + (size_t)row * DD;
    int i = threadIdx.x * 4;
    float4 xv = *(const float4*)(xr + i);
    float s  = xv.x + xv.y + xv.z + xv.w;
    float s2 = xv.x*xv.x + xv.y*xv.y + xv.z*xv.z + xv.w*xv.w;

    __shared__ float rs[8], rs2[8];
    __shared__ float smean, sinv;
    s  = warpReduceSum(s);
    s2 = warpReduceSum(s2);
    int w = threadIdx.x >> 5, l = threadIdx.x & 31;
    if (l == 0) { rs[w] = s; rs2[w] = s2; }
    __syncthreads();
    if (threadIdx.x == 0) {
        float S = 0.f, S2 = 0.f;
        #pragma unroll
        for (int k = 0; k < 8; k++) { S += rs[k]; S2 += rs2[k]; }
        float mean = S * (1.0f / (float)DD);
        float var  = (S2 - (float)DD * mean * mean) * (1.0f / (float)(DD - 1));
        var = fmaxf(var, 0.0f);
        smean = mean;
        sinv  = 1.0f / (sqrtf(var) + LN_EPS);
    }
    __syncthreads();
    float m = smean, inv = sinv;
    float4 av = *(const float4*)(alpha + i);
    float4 bv = *(const float4*)(beta  + i);
    float o0 = av.x * (xv.x - m) * inv + bv.x;
    float o1 = av.y * (xv.y - m) * inv + bv.y;
    float o2 = av.z * (xv.z - m) * inv + bv.z;
    float o3 = av.w * (xv.w - m) * inv + bv.w;
    bf16 h0 = __float2bfloat16(o0), h1 = __float2bfloat16(o1);
    bf16 h2 = __float2bfloat16(o2), h3 = __float2bfloat16(o3);
    bf16 l0 = __float2bfloat16(o0 - __bfloat162float(h0));
    bf16 l1 = __float2bfloat16(o1 - __bfloat162float(h1));
    bf16 l2 = __float2bfloat16(o2 - __bfloat162float(h2));
    bf16 l3 = __float2bfloat16(o3 - __bfloat162float(h3));
    size_t off = (size_t)row * DD + i;
    ((__nv_bfloat162*)(oh + off))[0] = __nv_bfloat162(h0, h1);
    ((__nv_bfloat162*)(oh + off))[1] = __nv_bfloat162(h2, h3);
    ((__nv_bfloat162*)(ol + off))[0] = __nv_bfloat162(l0, l1);
    ((__nv_bfloat162*)(ol + off))[1] = __nv_bfloat162(l2, l3);
}

// ---------------------------------------------------------------------------
// mma.sync split-bf16 GEMM: C[M,N] = (Ah+Al)[M,K] @ (Bh+Bl)[N,K]^T
//   acc += Ah*Bh + Ah*Bl + Al*Bh  (fp32 accumulators in registers)
// 128x128 tile, BK=32, 256 threads (8 warps, 4x2; 32x64 per warp),
// double-buffered cp.async. Epilogue: +bias, ReLU, +res, fp32 or bf16 pair.
// ---------------------------------------------------------------------------
#define BK 32
#define LDSX 40                       // padded row stride in bf16 elems (80B)
#define MATB (128 * LDSX * 2)         // 10240 B per matrix tile
#define STAGE (4 * MATB)              // Ah, Al, Bh, Bl
#define GEMM_SMEM (2 * STAGE)         // 81920 B

template<bool BIAS, bool RELU, bool RES, bool OUTPAIR>
__global__ __launch_bounds__(256) void gemm_mma(
    const bf16* __restrict__ Ah, const bf16* __restrict__ Al,
    const bf16* __restrict__ Bh, const bf16* __restrict__ Bl,
    const float* __restrict__ bias, const float* __restrict__ res,
    float* __restrict__ Cf, bf16* __restrict__ Ch, bf16* __restrict__ Cl,
    int M, int N, int K)
{
    extern __shared__ char sm_raw[];
    uint32_t sbase = smem_u32(sm_raw);

    int tid = threadIdx.x, lane = tid & 31, wid = tid >> 5;
    int m0 = blockIdx.y * 128, n0 = blockIdx.x * 128;
    int wm = wid & 3, wn = wid >> 2;      // warp grid 4 x 2
    int lr = lane >> 2, lk2 = (lane & 3) * 2;

    float acc[2][8][4];
    #pragma unroll
    for (int a = 0; a < 2; a++)
        #pragma unroll
        for (int b = 0; b < 8; b++)
            #pragma unroll
            for (int c = 0; c < 4; c++) acc[a][b][c] = 0.f;

    const int NC = K / BK;

    auto load_chunk = [&](int c, int buf) {
        int kc = c * BK;
        uint32_t base = sbase + buf * STAGE;
        #pragma unroll
        for (int T = 0; T < 4; T++) {
            const bf16* src = (T == 0) ? Ah : (T == 1) ? Al : (T == 2) ? Bh : Bl;
            int r0 = (T < 2) ? m0 : n0;
            uint32_t mb = base + T * MATB;
            #pragma unroll
            for (int i = 0; i < 2; i++) {
                int idx = tid + i * 256;           // 0..511
                int row = idx >> 2, c16 = idx & 3;
                cp16(mb + row * (LDSX * 2) + c16 * 16,
                     src + (size_t)(r0 + row) * K + kc + c16 * 8);
            }
        }
        cp_commit();
    };

    load_chunk(0, 0);
    if (NC > 1) load_chunk(1, 1);

    for (int c = 0; c < NC; c++) {
        if (c + 1 < NC) cp_wait<1>(); else cp_wait<0>();
        __syncthreads();

        const char* stg = sm_raw + (c & 1) * STAGE;
        const bf16* Ah_s = (const bf16*)(stg);
        const bf16* Al_s = (const bf16*)(stg + MATB);
        const bf16* Bh_s = (const bf16*)(stg + 2 * MATB);
        const bf16* Bl_s = (const bf16*)(stg + 3 * MATB);

        #pragma unroll
        for (int ks = 0; ks < 2; ks++) {
            int k0 = ks * 16 + lk2;
            uint32_t ahf[2][4], alf[2][4];
            #pragma unroll
            for (int mf = 0; mf < 2; mf++) {
                int r = wm * 32 + mf * 16 + lr;
                ahf[mf][0] = *(const uint32_t*)(Ah_s + r * LDSX + k0);
                ahf[mf][1] = *(const uint32_t*)(Ah_s + (r + 8) * LDSX + k0);
                ahf[mf][2] = *(const uint32_t*)(Ah_s + r * LDSX + k0 + 8);
                ahf[mf][3] = *(const uint32_t*)(Ah_s + (r + 8) * LDSX + k0 + 8);
                alf[mf][0] = *(const uint32_t*)(Al_s + r * LDSX + k0);
                alf[mf][1] = *(const uint32_t*)(Al_s + (r + 8) * LDSX + k0);
                alf[mf][2] = *(const uint32_t*)(Al_s + r * LDSX + k0 + 8);
                alf[mf][3] = *(const uint32_t*)(Al_s + (r + 8) * LDSX + k0 + 8);
            }
            #pragma unroll
            for (int nf = 0; nf < 8; nf++) {
                int n = wn * 64 + nf * 8 + lr;
                uint32_t bh[2], bl[2];
                bh[0] = *(const uint32_t*)(Bh_s + n * LDSX + k0);
                bh[1] = *(const uint32_t*)(Bh_s + n * LDSX + k0 + 8);
                bl[0] = *(const uint32_t*)(Bl_s + n * LDSX + k0);
                bl[1] = *(const uint32_t*)(Bl_s + n * LDSX + k0 + 8);
                mma16816(acc[0][nf], ahf[0], bh);
                mma16816(acc[1][nf], ahf[1], bh);
                mma16816(acc[0][nf], ahf[0], bl);
                mma16816(acc[1][nf], ahf[1], bl);
                mma16816(acc[0][nf], alf[0], bh);
                mma16816(acc[1][nf], alf[1], bh);
            }
        }
        __syncthreads();
        if (c + 2 < NC) load_chunk(c + 2, c & 1);
    }

    // epilogue
    #pragma unroll
    for (int mf = 0; mf < 2; mf++) {
        int r0 = m0 + wm * 32 + mf * 16 + lr;
        #pragma unroll
        for (int nf = 0; nf < 8; nf++) {
            int col = n0 + wn * 64 + nf * 8 + lk2;
            float* cc = acc[mf][nf];
            float v00 = cc[0], v01 = cc[1], v10 = cc[2], v11 = cc[3];
            if (BIAS) {
                float b0 = __ldg(bias + col), b1 = __ldg(bias + col + 1);
                v00 += b0; v01 += b1; v10 += b0; v11 += b1;
            }
            if (RELU) {
                v00 = fmaxf(v00, 0.f); v01 = fmaxf(v01, 0.f);
                v10 = fmaxf(v10, 0.f); v11 = fmaxf(v11, 0.f);
            }
            if (RES) {
                float2 ra = *(const float2*)(res + (size_t)r0 * N + col);
                float2 rb = *(const float2*)(res + (size_t)(r0 + 8) * N + col);
                v00 += ra.x; v01 += ra.y; v10 += rb.x; v11 += rb.y;
            }
            if (OUTPAIR) {
                bf16 h00 = __float2bfloat16(v00), h01 = __float2bfloat16(v01);
                bf16 h10 = __float2bfloat16(v10), h11 = __float2bfloat16(v11);
                bf16 l00 = __float2bfloat16(v00 - __bfloat162float(h00));
                bf16 l01 = __float2bfloat16(v01 - __bfloat162float(h01));
                bf16 l10 = __float2bfloat16(v10 - __bfloat162float(h10));
                bf16 l11 = __float2bfloat16(v11 - __bfloat162float(h11));
                *(__nv_bfloat162*)(Ch + (size_t)r0 * N + col)       = __nv_bfloat162(h00, h01);
                *(__nv_bfloat162*)(Ch + (size_t)(r0 + 8) * N + col) = __nv_bfloat162(h10, h11);
                *(__nv_bfloat162*)(Cl + (size_t)r0 * N + col)       = __nv_bfloat162(l00, l01);
                *(__nv_bfloat162*)(Cl + (size_t)(r0 + 8) * N + col) = __nv_bfloat162(l10, l11);
            } else {
                *(float2*)(Cf + (size_t)r0 * N + col)       = make_float2(v00, v01);
                *(float2*)(Cf + (size_t)(r0 + 8) * N + col) = make_float2(v10, v11);
            }
        }
    }
}

// ---------------------------------------------------------------------------
// Attention: one block per (b, h, 16-query tile). 512 threads.
// fp32 two-pass softmax, full score tile in smem. Output: bf16 (hi,lo) pair.
// ---------------------------------------------------------------------------
#define QT 16
#define ATHR 512
#define ATTN_SMEM_FLOATS (QT*SS + QT*64 + 8*QT*64 + QT)
#define ATTN_SMEM_BYTES  (ATTN_SMEM_FLOATS * 4)

__global__ __launch_bounds__(ATHR) void attn_k(
    const float* __restrict__ q, const float* __restrict__ k,
    const float* __restrict__ v, const int* __restrict__ mask,
    bf16* __restrict__ avh, bf16* __restrict__ avl)
{
    extern __shared__ float sm[];
    float* sc   = sm;                       // QT*2048
    float* qs   = sc + QT * SS;             // QT*64
    float* part = qs + QT * 64;             // 8*QT*64
    float* rinv = part + 8 * QT * 64;       // QT

    int t   = threadIdx.x;
    int blk = blockIdx.x;
    int qt  = blk & 127;
    int bh  = blk >> 7;
    int h   = bh & (HH - 1), b = bh >> 4;
    int q0  = qt * QT;
    size_t base = (size_t)b * SS * DD + (size_t)h * DKK;

    // load Q tile (16x64)
    {
        int r = t >> 5;               // 0..15
        int c = (t & 31) * 2;         // 0..62
        *(float2*)(qs + r * 64 + c) =
            *(const float2*)(q + base + (size_t)(q0 + r) * DD + c);
    }
    __syncthreads();

    // scores
    const int* mk = mask + b * SS;
    for (int j = t; j < SS; j += ATHR) {
        const float* kr = k + base + (size_t)j * DD;
        float acc[QT];
        #pragma unroll
        for (int r = 0; r < QT; r++) acc[r] = 0.f;
        #pragma unroll
        for (int c = 0; c < DKK; c += 4) {
            float4 kv = *(const float4*)(kr + c);
            #pragma unroll
            for (int r = 0; r < QT; r++) {
                const float* qr = qs + r * 64 + c;
                acc[r] += qr[0]*kv.x + qr[1]*kv.y + qr[2]*kv.z + qr[3]*kv.w;
            }
        }
        bool dead = (mk[j] == 0);
        #pragma unroll
        for (int r = 0; r < QT; r++)
            sc[r * SS + j] = dead ? -1e9f : acc[r] * 0.125f;
    }
    __syncthreads();

    // softmax: 16 warps, one row each
    int w = t >> 5, l = t & 31;
    {
        float* s = sc + w * SS;
        float m = -1e30f;
        for (int j = l; j < SS; j += 32) m = fmaxf(m, s[j]);
        m = warpReduceMax(m);
        float sum = 0.f;
        for (int j = l; j < SS; j += 32) {
            float e = __expf(s[j] - m);
            s[j] = e;
            sum += e;
        }
        sum = warpReduceSum(sum);
        if (l == 0) rinv[w] = 1.0f / sum;
    }
    __syncthreads();

    // AV: 8 groups x 64 lanes; group g handles keys [g*256, g*256+256)
    int d = t & 63, g = t >> 6;
    const float* vp = v + base + d;
    float acc[QT];
    #pragma unroll
    for (int r = 0; r < QT; r++) acc[r] = 0.f;
    for (int j0 = g * 256; j0 < g * 256 + 256; j0 += 4) {
        float v0 = vp[(size_t)(j0+0) * DD];
        float v1 = vp[(size_t)(j0+1) * DD];
        float v2 = vp[(size_t)(j0+2) * DD];
        float v3 = vp[(size_t)(j0+3) * DD];
        #pragma unroll
        for (int r = 0; r < QT; r++) {
            float4 s4 = *(const float4*)(sc + r * SS + j0);
            acc[r] += s4.x*v0 + s4.y*v1 + s4.z*v2 + s4.w*v3;
        }
    }
    #pragma unroll
    for (int r = 0; r < QT; r++) part[(g * QT + r) * 64 + d] = acc[r];
    __syncthreads();

    // combine + write bf16 pair
    for (int idx = t; idx < QT * 64; idx += ATHR) {
        int r = idx >> 6, dd = idx & 63;
        float s = 0.f;
        #pragma unroll
        for (int gg = 0; gg < 8; gg++) s += part[(gg * QT + r) * 64 + dd];
        s *= rinv[r];
        bf16 hh = __float2bfloat16(s);
        size_t off = base + (size_t)(q0 + r) * DD + dd;
        avh[off] = hh;
        avl[off] = __float2bfloat16(s - __bfloat162float(hh));
    }
}

// ---------------------------------------------------------------------------
// Driver
// ---------------------------------------------------------------------------
extern "C" void kernel_launch(void* const* d_in, const int* in_sizes, int n_in,
                              void* d_out, int out_size)
{
    const float* x      = (const float*)d_in[0];
    const int*   mask   = (const int*)  d_in[1];
    const float* wq     = (const float*)d_in[2];
    const float* wk     = (const float*)d_in[3];
    const float* wv     = (const float*)d_in[4];
    const float* wo     = (const float*)d_in[5];
    const float* w1     = (const float*)d_in[6];
    const float* b1     = (const float*)d_in[7];
    const float* w2     = (const float*)d_in[8];
    const float* b2     = (const float*)d_in[9];
    const float* alpha1 = (const float*)d_in[10];
    const float* bias1  = (const float*)d_in[11];
    const float* alpha2 = (const float*)d_in[12];
    const float* bias2  = (const float*)d_in[13];
    float* out = (float*)d_out;

    bf16 *xnh, *xnl, *avh, *avl, *xn2h, *xn2l, *hbh, *hbl;
    bf16 *wqh, *wql, *wkh, *wkl, *wvh, *wvl, *woh, *wol, *w1h, *w1l, *w2h, *w2l;
    float *qb, *kb, *vb, *x1;
    cudaGetSymbolAddress((void**)&xnh,  g_xnh);  cudaGetSymbolAddress((void**)&xnl,  g_xnl);
    cudaGetSymbolAddress((void**)&qb,   g_q);    cudaGetSymbolAddress((void**)&kb,   g_kk);
    cudaGetSymbolAddress((void**)&vb,   g_vv);
    cudaGetSymbolAddress((void**)&avh,  g_avh);  cudaGetSymbolAddress((void**)&avl,  g_avl);
    cudaGetSymbolAddress((void**)&x1,   g_x1);
    cudaGetSymbolAddress((void**)&xn2h, g_xn2h); cudaGetSymbolAddress((void**)&xn2l, g_xn2l);
    cudaGetSymbolAddress((void**)&hbh,  g_hbh);  cudaGetSymbolAddress((void**)&hbl,  g_hbl);
    cudaGetSymbolAddress((void**)&wqh,  g_wqh);  cudaGetSymbolAddress((void**)&wql,  g_wql);
    cudaGetSymbolAddress((void**)&wkh,  g_wkh);  cudaGetSymbolAddress((void**)&wkl,  g_wkl);
    cudaGetSymbolAddress((void**)&wvh,  g_wvh);  cudaGetSymbolAddress((void**)&wvl,  g_wvl);
    cudaGetSymbolAddress((void**)&woh,  g_woh);  cudaGetSymbolAddress((void**)&wol,  g_wol);
    cudaGetSymbolAddress((void**)&w1h,  g_w1h);  cudaGetSymbolAddress((void**)&w1l,  g_w1l);
    cudaGetSymbolAddress((void**)&w2h,  g_w2h);  cudaGetSymbolAddress((void**)&w2l,  g_w2l);

    cudaFuncSetAttribute(attn_k, cudaFuncAttributeMaxDynamicSharedMemorySize,
                         ATTN_SMEM_BYTES);
    cudaFuncSetAttribute(gemm_mma<false,false,false,false>,
                         cudaFuncAttributeMaxDynamicSharedMemorySize, GEMM_SMEM);
    cudaFuncSetAttribute(gemm_mma<false,false,true,false>,
                         cudaFuncAttributeMaxDynamicSharedMemorySize, GEMM_SMEM);
    cudaFuncSetAttribute(gemm_mma<true,true,false,true>,
                         cudaFuncAttributeMaxDynamicSharedMemorySize, GEMM_SMEM);
    cudaFuncSetAttribute(gemm_mma<true,false,true,false>,
                         cudaFuncAttributeMaxDynamicSharedMemorySize, GEMM_SMEM);

    // 0. split weights to bf16 hi/lo
    split_k<<<(DD*DD/4 + 255)/256, 256>>>(wq, wqh, wql, DD*DD/4);
    split_k<<<(DD*DD/4 + 255)/256, 256>>>(wk, wkh, wkl, DD*DD/4);
    split_k<<<(DD*DD/4 + 255)/256, 256>>>(wv, wvh, wvl, DD*DD/4);
    split_k<<<(DD*DD/4 + 255)/256, 256>>>(wo, woh, wol, DD*DD/4);
    split_k<<<(DFFN*DD/4 + 255)/256, 256>>>(w1, w1h, w1l, DFFN*DD/4);
    split_k<<<(DD*DFFN/4 + 255)/256, 256>>>(w2, w2h, w2l, DD*DFFN/4);

    // 1. LN1 -> bf16 pair
    layernorm_k<<<NTOK, 256>>>(x, alpha1, bias1, xnh, xnl);

    // 2-4. Q, K, V projections (fp32 out)
    dim3 gProj(DD / 128, NTOK / 128);       // (8, 32)
    gemm_mma<false,false,false,false><<<gProj, 256, GEMM_SMEM>>>(
        xnh, xnl, wqh, wql, nullptr, nullptr, qb, nullptr, nullptr, NTOK, DD, DD);
    gemm_mma<false,false,false,false><<<gProj, 256, GEMM_SMEM>>>(
        xnh, xnl, wkh, wkl, nullptr, nullptr, kb, nullptr, nullptr, NTOK, DD, DD);
    gemm_mma<false,false,false,false><<<gProj, 256, GEMM_SMEM>>>(
        xnh, xnl, wvh, wvl, nullptr, nullptr, vb, nullptr, nullptr, NTOK, DD, DD);

    // 5. attention -> bf16 pair
    attn_k<<<BB * HH * (SS / QT), ATHR, ATTN_SMEM_BYTES>>>(qb, kb, vb, mask, avh, avl);

    // 6. output projection + residual(x) -> x1 fp32
    gemm_mma<false,false,true,false><<<gProj, 256, GEMM_SMEM>>>(
        avh, avl, woh, wol, nullptr, x, x1, nullptr, nullptr, NTOK, DD, DD);

    // 7. LN2 -> bf16 pair
    layernorm_k<<<NTOK, 256>>>(x1, alpha2, bias2, xn2h, xn2l);

    // 8. FFN up: relu(xn2@w1^T + b1) -> bf16 pair
    dim3 gF1(DFFN / 128, NTOK / 128);       // (32, 32)
    gemm_mma<true,true,false,true><<<gF1, 256, GEMM_SMEM>>>(
        xn2h, xn2l, w1h, w1l, b1, nullptr, nullptr, hbh, hbl, NTOK, DFFN, DD);

    // 9. FFN down: h@w2^T + b2 + x1 -> out fp32
    gemm_mma<true,false,true,false><<<gProj, 256, GEMM_SMEM>>>(
        hbh, hbl, w2h, w2l, b2, x1, out, nullptr, nullptr, NTOK, DD, DFFN);
}

// round 4
// speedup vs baseline: 4.1358x; 2.2966x over previous
#include <cuda_runtime.h>
#include <cuda_bf16.h>
#include <math.h>
#include <stdint.h>

// Problem constants
#define BB 2
#define SS 2048
#define DD 1024
#define HH 16
#define DKK 64
#define DFFN 4096
#define NTOK (BB*SS)          // 4096
#define LN_EPS 1e-6f

typedef __nv_bfloat16 bf16;

// ---------------------------------------------------------------------------
// Scratch (static __device__ arrays: allocation-guard-safe)
// ---------------------------------------------------------------------------
__device__ bf16  g_xnh [(size_t)NTOK*DD],  g_xnl [(size_t)NTOK*DD];
__device__ bf16  g_qb  [(size_t)NTOK*DD];
__device__ bf16  g_kb  [(size_t)NTOK*DD];
__device__ bf16  g_vb  [(size_t)NTOK*DD];
__device__ bf16  g_avh [(size_t)NTOK*DD],  g_avl [(size_t)NTOK*DD];
__device__ float g_x1  [(size_t)NTOK*DD];
__device__ bf16  g_xn2h[(size_t)NTOK*DD],  g_xn2l[(size_t)NTOK*DD];
__device__ bf16  g_hbh [(size_t)NTOK*DFFN], g_hbl[(size_t)NTOK*DFFN];
__device__ bf16  g_wqh [(size_t)DD*DD],   g_wql [(size_t)DD*DD];
__device__ bf16  g_wkh [(size_t)DD*DD],   g_wkl [(size_t)DD*DD];
__device__ bf16  g_wvh [(size_t)DD*DD],   g_wvl [(size_t)DD*DD];
__device__ bf16  g_woh [(size_t)DD*DD],   g_wol [(size_t)DD*DD];
__device__ bf16  g_w1h [(size_t)DFFN*DD], g_w1l [(size_t)DFFN*DD];
__device__ bf16  g_w2h [(size_t)DD*DFFN], g_w2l [(size_t)DD*DFFN];

// ---------------------------------------------------------------------------
// PTX helpers (cp.async + mma.sync + ldmatrix)
// ---------------------------------------------------------------------------
__device__ __forceinline__ uint32_t smem_u32(const void* p) {
    uint32_t a;
    asm("{ .reg .u64 t; cvta.to.shared.u64 t, %1; cvt.u32.u64 %0, t; }"
        : "=r"(a) : "l"(p));
    return a;
}
__device__ __forceinline__ void cp16(uint32_t d, const void* s) {
    asm volatile("cp.async.cg.shared.global [%0], [%1], 16;\n" :: "r"(d), "l"(s));
}
__device__ __forceinline__ void cp_commit() { asm volatile("cp.async.commit_group;\n" ::); }
template<int N> __device__ __forceinline__ void cp_wait() {
    asm volatile("cp.async.wait_group %0;\n" :: "n"(N));
}

__device__ __forceinline__ void mma16816(float* c, const uint32_t* a, const uint32_t* b) {
    asm volatile(
        "mma.sync.aligned.m16n8k16.row.col.f32.bf16.bf16.f32 "
        "{%0,%1,%2,%3}, {%4,%5,%6,%7}, {%8,%9}, {%0,%1,%2,%3};"
        : "+f"(c[0]), "+f"(c[1]), "+f"(c[2]), "+f"(c[3])
        : "r"(a[0]), "r"(a[1]), "r"(a[2]), "r"(a[3]), "r"(b[0]), "r"(b[1]));
}
__device__ __forceinline__ void ldsm4(uint32_t* r, uint32_t addr) {
    asm volatile("ldmatrix.sync.aligned.m8n8.x4.shared.b16 {%0,%1,%2,%3}, [%4];"
        : "=r"(r[0]), "=r"(r[1]), "=r"(r[2]), "=r"(r[3]) : "r"(addr));
}
__device__ __forceinline__ void ldsm4t(uint32_t* r, uint32_t addr) {
    asm volatile("ldmatrix.sync.aligned.m8n8.x4.trans.shared.b16 {%0,%1,%2,%3}, [%4];"
        : "=r"(r[0]), "=r"(r[1]), "=r"(r[2]), "=r"(r[3]) : "r"(addr));
}
__device__ __forceinline__ uint32_t packbf(float lo, float hi) {
    __nv_bfloat162 t = __floats2bfloat162_rn(lo, hi);
    return *(uint32_t*)&t;
}

// ---------------------------------------------------------------------------
// Reductions
// ---------------------------------------------------------------------------
__device__ __forceinline__ float warpReduceSum(float v) {
    #pragma unroll
    for (int o = 16; o > 0; o >>= 1) v += __shfl_xor_sync(0xffffffffu, v, o);
    return v;
}

// ---------------------------------------------------------------------------
// Split fp32 -> bf16 (hi, lo). n4 = n/4.
// ---------------------------------------------------------------------------
__global__ __launch_bounds__(256) void split_k(
    const float* __restrict__ w, bf16* __restrict__ hi,
    bf16* __restrict__ lo, int n4)
{
    int i = blockIdx.x * 256 + threadIdx.x;
    if (i >= n4) return;
    float4 v = ((const float4*)w)[i];
    bf16 h0 = __float2bfloat16(v.x), h1 = __float2bfloat16(v.y);
    bf16 h2 = __float2bfloat16(v.z), h3 = __float2bfloat16(v.w);
    bf16 l0 = __float2bfloat16(v.x - __bfloat162float(h0));
    bf16 l1 = __float2bfloat16(v.y - __bfloat162float(h1));
    bf16 l2 = __float2bfloat16(v.z - __bfloat162float(h2));
    bf16 l3 = __float2bfloat16(v.w - __bfloat162float(h3));
    __nv_bfloat162* hp = (__nv_bfloat162*)hi;
    __nv_bfloat162* lp = (__nv_bfloat162*)lo;
    hp[i*2]   = __nv_bfloat162(h0, h1);
    hp[i*2+1] = __nv_bfloat162(h2, h3);
    lp[i*2]   = __nv_bfloat162(l0, l1);
    lp[i*2+1] = __nv_bfloat162(l2, l3);
}

// ---------------------------------------------------------------------------
// LayerNorm -> bf16 (hi, lo) pair. One 256-thread block per row of 1024.
// torch semantics: alpha * (x - mean) / (sqrt(var_unbiased) + eps) + bias
// ---------------------------------------------------------------------------
__global__ __launch_bounds__(256) void layernorm_k(
    const float* __restrict__ x, const float* __restrict__ alpha,
    const float* __restrict__ beta,
    bf16* __restrict__ oh, bf16* __restrict__ ol)
{
    int row = blockIdx.x;
    const float* xr = x + (size_t)row * DD;
    int i = threadIdx.x * 4;
    float4 xv = *(const float4*)(xr + i);
    float s  = xv.x + xv.y + xv.z + xv.w;
    float s2 = xv.x*xv.x + xv.y*xv.y + xv.z*xv.z + xv.w*xv.w;

    __shared__ float rs[8], rs2[8];
    __shared__ float smean, sinv;
    s  = warpReduceSum(s);
    s2 = warpReduceSum(s2);
    int w = threadIdx.x >> 5, l = threadIdx.x & 31;
    if (l == 0) { rs[w] = s; rs2[w] = s2; }
    __syncthreads();
    if (threadIdx.x == 0) {
        float S = 0.f, S2 = 0.f;
        #pragma unroll
        for (int k = 0; k < 8; k++) { S += rs[k]; S2 += rs2[k]; }
        float mean = S * (1.0f / (float)DD);
        float var  = (S2 - (float)DD * mean * mean) * (1.0f / (float)(DD - 1));
        var = fmaxf(var, 0.0f);
        smean = mean;
        sinv  = 1.0f / (sqrtf(var) + LN_EPS);
    }
    __syncthreads();
    float m = smean, inv = sinv;
    float4 av = *(const float4*)(alpha + i);
    float4 bv = *(const float4*)(beta  + i);
    float o0 = av.x * (xv.x - m) * inv + bv.x;
    float o1 = av.y * (xv.y - m) * inv + bv.y;
    float o2 = av.z * (xv.z - m) * inv + bv.z;
    float o3 = av.w * (xv.w - m) * inv + bv.w;
    bf16 h0 = __float2bfloat16(o0), h1 = __float2bfloat16(o1);
    bf16 h2 = __float2bfloat16(o2), h3 = __float2bfloat16(o3);
    bf16 l0 = __float2bfloat16(o0 - __bfloat162float(h0));
    bf16 l1 = __float2bfloat16(o1 - __bfloat162float(h1));
    bf16 l2 = __float2bfloat16(o2 - __bfloat162float(h2));
    bf16 l3 = __float2bfloat16(o3 - __bfloat162float(h3));
    size_t off = (size_t)row * DD + i;
    ((__nv_bfloat162*)(oh + off))[0] = __nv_bfloat162(h0, h1);
    ((__nv_bfloat162*)(oh + off))[1] = __nv_bfloat162(h2, h3);
    ((__nv_bfloat162*)(ol + off))[0] = __nv_bfloat162(l0, l1);
    ((__nv_bfloat162*)(ol + off))[1] = __nv_bfloat162(l2, l3);
}

// ---------------------------------------------------------------------------
// mma.sync split-bf16 GEMM: C[M,N] = (Ah+Al)[M,K] @ (Bh+Bl)[N,K]^T
//   acc += Ah*Bh + Ah*Bl + Al*Bh  (fp32 accumulators in registers)
// 128x128 tile, BK=32, 256 threads (8 warps, 4x2; 32x64 per warp),
// double-buffered cp.async. OUTM: 0=f32, 1=bf16 hi/lo pair, 2=bf16 single.
// ---------------------------------------------------------------------------
#define BK 32
#define LDSX 40                       // padded row stride in bf16 elems (80B)
#define MATB (128 * LDSX * 2)         // 10240 B per matrix tile
#define STAGE (4 * MATB)              // Ah, Al, Bh, Bl
#define GEMM_SMEM (2 * STAGE)         // 81920 B

template<bool BIAS, bool RELU, bool RES, int OUTM>
__global__ __launch_bounds__(256) void gemm_mma(
    const bf16* __restrict__ Ah, const bf16* __restrict__ Al,
    const bf16* __restrict__ Bh, const bf16* __restrict__ Bl,
    const float* __restrict__ bias, const float* __restrict__ res,
    float* __restrict__ Cf, bf16* __restrict__ Ch, bf16* __restrict__ Cl,
    int M, int N, int K)
{
    extern __shared__ char sm_raw[];
    uint32_t sbase = smem_u32(sm_raw);

    int tid = threadIdx.x, lane = tid & 31, wid = tid >> 5;
    int m0 = blockIdx.y * 128, n0 = blockIdx.x * 128;
    int wm = wid & 3, wn = wid >> 2;      // warp grid 4 x 2
    int lr = lane >> 2, lk2 = (lane & 3) * 2;

    float acc[2][8][4];
    #pragma unroll
    for (int a = 0; a < 2; a++)
        #pragma unroll
        for (int b = 0; b < 8; b++)
            #pragma unroll
            for (int c = 0; c < 4; c++) acc[a][b][c] = 0.f;

    const int NC = K / BK;

    auto load_chunk = [&](int c, int buf) {
        int kc = c * BK;
        uint32_t base = sbase + buf * STAGE;
        #pragma unroll
        for (int T = 0; T < 4; T++) {
            const bf16* src = (T == 0) ? Ah : (T == 1) ? Al : (T == 2) ? Bh : Bl;
            int r0 = (T < 2) ? m0 : n0;
            uint32_t mb = base + T * MATB;
            #pragma unroll
            for (int i = 0; i < 2; i++) {
                int idx = tid + i * 256;           // 0..511
                int row = idx >> 2, c16 = idx & 3;
                cp16(mb + row * (LDSX * 2) + c16 * 16,
                     src + (size_t)(r0 + row) * K + kc + c16 * 8);
            }
        }
        cp_commit();
    };

    load_chunk(0, 0);
    if (NC > 1) load_chunk(1, 1);

    for (int c = 0; c < NC; c++) {
        if (c + 1 < NC) cp_wait<1>(); else cp_wait<0>();
        __syncthreads();

        const char* stg = sm_raw + (c & 1) * STAGE;
        const bf16* Ah_s = (const bf16*)(stg);
        const bf16* Al_s = (const bf16*)(stg + MATB);
        const bf16* Bh_s = (const bf16*)(stg + 2 * MATB);
        const bf16* Bl_s = (const bf16*)(stg + 3 * MATB);

        #pragma unroll
        for (int ks = 0; ks < 2; ks++) {
            int k0 = ks * 16 + lk2;
            uint32_t ahf[2][4], alf[2][4];
            #pragma unroll
            for (int mf = 0; mf < 2; mf++) {
                int r = wm * 32 + mf * 16 + lr;
                ahf[mf][0] = *(const uint32_t*)(Ah_s + r * LDSX + k0);
                ahf[mf][1] = *(const uint32_t*)(Ah_s + (r + 8) * LDSX + k0);
                ahf[mf][2] = *(const uint32_t*)(Ah_s + r * LDSX + k0 + 8);
                ahf[mf][3] = *(const uint32_t*)(Ah_s + (r + 8) * LDSX + k0 + 8);
                alf[mf][0] = *(const uint32_t*)(Al_s + r * LDSX + k0);
                alf[mf][1] = *(const uint32_t*)(Al_s + (r + 8) * LDSX + k0);
                alf[mf][2] = *(const uint32_t*)(Al_s + r * LDSX + k0 + 8);
                alf[mf][3] = *(const uint32_t*)(Al_s + (r + 8) * LDSX + k0 + 8);
            }
            #pragma unroll
            for (int nf = 0; nf < 8; nf++) {
                int n = wn * 64 + nf * 8 + lr;
                uint32_t bh[2], bl[2];
                bh[0] = *(const uint32_t*)(Bh_s + n * LDSX + k0);
                bh[1] = *(const uint32_t*)(Bh_s + n * LDSX + k0 + 8);
                bl[0] = *(const uint32_t*)(Bl_s + n * LDSX + k0);
                bl[1] = *(const uint32_t*)(Bl_s + n * LDSX + k0 + 8);
                mma16816(acc[0][nf], ahf[0], bh);
                mma16816(acc[1][nf], ahf[1], bh);
                mma16816(acc[0][nf], ahf[0], bl);
                mma16816(acc[1][nf], ahf[1], bl);
                mma16816(acc[0][nf], alf[0], bh);
                mma16816(acc[1][nf], alf[1], bh);
            }
        }
        __syncthreads();
        if (c + 2 < NC) load_chunk(c + 2, c & 1);
    }

    // epilogue
    #pragma unroll
    for (int mf = 0; mf < 2; mf++) {
        int r0 = m0 + wm * 32 + mf * 16 + lr;
        #pragma unroll
        for (int nf = 0; nf < 8; nf++) {
            int col = n0 + wn * 64 + nf * 8 + lk2;
            float* cc = acc[mf][nf];
            float v00 = cc[0], v01 = cc[1], v10 = cc[2], v11 = cc[3];
            if (BIAS) {
                float b0 = __ldg(bias + col), b1 = __ldg(bias + col + 1);
                v00 += b0; v01 += b1; v10 += b0; v11 += b1;
            }
            if (RELU) {
                v00 = fmaxf(v00, 0.f); v01 = fmaxf(v01, 0.f);
                v10 = fmaxf(v10, 0.f); v11 = fmaxf(v11, 0.f);
            }
            if (RES) {
                float2 ra = *(const float2*)(res + (size_t)r0 * N + col);
                float2 rb = *(const float2*)(res + (size_t)(r0 + 8) * N + col);
                v00 += ra.x; v01 += ra.y; v10 += rb.x; v11 += rb.y;
            }
            if (OUTM == 1) {
                bf16 h00 = __float2bfloat16(v00), h01 = __float2bfloat16(v01);
                bf16 h10 = __float2bfloat16(v10), h11 = __float2bfloat16(v11);
                bf16 l00 = __float2bfloat16(v00 - __bfloat162float(h00));
                bf16 l01 = __float2bfloat16(v01 - __bfloat162float(h01));
                bf16 l10 = __float2bfloat16(v10 - __bfloat162float(h10));
                bf16 l11 = __float2bfloat16(v11 - __bfloat162float(h11));
                *(__nv_bfloat162*)(Ch + (size_t)r0 * N + col)       = __nv_bfloat162(h00, h01);
                *(__nv_bfloat162*)(Ch + (size_t)(r0 + 8) * N + col) = __nv_bfloat162(h10, h11);
                *(__nv_bfloat162*)(Cl + (size_t)r0 * N + col)       = __nv_bfloat162(l00, l01);
                *(__nv_bfloat162*)(Cl + (size_t)(r0 + 8) * N + col) = __nv_bfloat162(l10, l11);
            } else if (OUTM == 2) {
                *(__nv_bfloat162*)(Ch + (size_t)r0 * N + col) =
                    __floats2bfloat162_rn(v00, v01);
                *(__nv_bfloat162*)(Ch + (size_t)(r0 + 8) * N + col) =
                    __floats2bfloat162_rn(v10, v11);
            } else {
                *(float2*)(Cf + (size_t)r0 * N + col)       = make_float2(v00, v01);
                *(float2*)(Cf + (size_t)(r0 + 8) * N + col) = make_float2(v10, v11);
            }
        }
    }
}

// ---------------------------------------------------------------------------
// Flash attention (bf16 mma.sync): one CTA per (b, h, 128-query tile).
// 8 warps x 16 Q rows. K/V chunks of 64 keys, cp.async double-buffered.
// Online softmax in registers. Output: bf16 (hi,lo) pair.
// ---------------------------------------------------------------------------
#define AKST 72                       // smem row stride in bf16 (144 B)

__global__ __launch_bounds__(256) void fattn_k(
    const bf16* __restrict__ qg, const bf16* __restrict__ kg,
    const bf16* __restrict__ vg, const int* __restrict__ mask,
    bf16* __restrict__ avh, bf16* __restrict__ avl)
{
    __shared__ __align__(16) bf16 Ks[2][64 * AKST];
    __shared__ __align__(16) bf16 Vs[2][64 * AKST];
    __shared__ __align__(16) int  Msk[2][64];

    int t = threadIdx.x, lane = t & 31, w = t >> 5;
    int h = blockIdx.y & (HH - 1), b = blockIdx.y >> 4;
    size_t base = (size_t)b * SS * DD + h * DKK;
    int q0 = blockIdx.x * 128 + w * 16;
    int lr = lane >> 2, q4 = lane & 3;
    int l7 = lane & 7, lg8 = (lane >> 3) & 1, lg16 = (lane >> 4) & 1;

    // Q fragments (A-frag layout), loaded once from global
    uint32_t qf[4][4];
    #pragma unroll
    for (int ks = 0; ks < 4; ks++) {
        int col = ks * 16 + q4 * 2;
        qf[ks][0] = *(const uint32_t*)(qg + base + (size_t)(q0 + lr) * DD + col);
        qf[ks][1] = *(const uint32_t*)(qg + base + (size_t)(q0 + lr + 8) * DD + col);
        qf[ks][2] = *(const uint32_t*)(qg + base + (size_t)(q0 + lr) * DD + col + 8);
        qf[ks][3] = *(const uint32_t*)(qg + base + (size_t)(q0 + lr + 8) * DD + col + 8);
    }

    float vacc[8][4];
    #pragma unroll
    for (int nf = 0; nf < 8; nf++)
        #pragma unroll
        for (int c = 0; c < 4; c++) vacc[nf][c] = 0.f;
    float m0 = -1e30f, m1 = -1e30f, l0 = 0.f, l1 = 0.f;

    const int NC = SS / 64;           // 32 chunks

    auto load_chunk = [&](int c, int buf) {
        int key0 = c * 64;
        uint32_t kbAddr = smem_u32(&Ks[buf][0]);
        uint32_t vbAddr = smem_u32(&Vs[buf][0]);
        #pragma unroll
        for (int i = 0; i < 2; i++) {
            int idx = t * 2 + i;           // 0..511
            int row = idx >> 3, seg = idx & 7;
            cp16(kbAddr + row * (AKST * 2) + seg * 16,
                 kg + base + (size_t)(key0 + row) * DD + seg * 8);
            cp16(vbAddr + row * (AKST * 2) + seg * 16,
                 vg + base + (size_t)(key0 + row) * DD + seg * 8);
        }
        if (t < 16)
            cp16(smem_u32(&Msk[buf][0]) + t * 16, mask + b * SS + key0 + t * 4);
        cp_commit();
    };

    load_chunk(0, 0);
    load_chunk(1, 1);

    for (int c = 0; c < NC; c++) {
        if (c + 1 < NC) cp_wait<1>(); else cp_wait<0>();
        __syncthreads();
        int buf = c & 1;

        // --- scores: S = Q K^T ---
        float sacc[8][4];
        #pragma unroll
        for (int nf = 0; nf < 8; nf++)
            #pragma unroll
            for (int cc = 0; cc < 4; cc++) sacc[nf][cc] = 0.f;

        uint32_t ksb = smem_u32(&Ks[buf][0]);
        #pragma unroll
        for (int ks = 0; ks < 4; ks++) {
            #pragma unroll
            for (int nfp = 0; nfp < 4; nfp++) {
                uint32_t kf[4];
                uint32_t addr = ksb
                    + (uint32_t)(nfp * 16 + lg16 * 8 + l7) * (AKST * 2)
                    + ks * 32 + lg8 * 16;
                ldsm4(kf, addr);
                mma16816(sacc[2*nfp],     qf[ks], kf);
                mma16816(sacc[2*nfp + 1], qf[ks], kf + 2);
            }
        }

        // --- scale + mask ---
        #pragma unroll
        for (int nf = 0; nf < 8; nf++) {
            int col = nf * 8 + q4 * 2;
            int mk0 = Msk[buf][col], mk1 = Msk[buf][col + 1];
            float s0 = sacc[nf][0] * 0.125f, s1 = sacc[nf][1] * 0.125f;
            float s2 = sacc[nf][2] * 0.125f, s3 = sacc[nf][3] * 0.125f;
            sacc[nf][0] = mk0 ? s0 : -1e9f;
            sacc[nf][1] = mk1 ? s1 : -1e9f;
            sacc[nf][2] = mk0 ? s2 : -1e9f;
            sacc[nf][3] = mk1 ? s3 : -1e9f;
        }

        // --- online softmax ---
        float cm0 = -1e30f, cm1 = -1e30f;
        #pragma unroll
        for (int nf = 0; nf < 8; nf++) {
            cm0 = fmaxf(cm0, fmaxf(sacc[nf][0], sacc[nf][1]));
            cm1 = fmaxf(cm1, fmaxf(sacc[nf][2], sacc[nf][3]));
        }
        cm0 = fmaxf(cm0, __shfl_xor_sync(0xffffffffu, cm0, 1));
        cm0 = fmaxf(cm0, __shfl_xor_sync(0xffffffffu, cm0, 2));
        cm1 = fmaxf(cm1, __shfl_xor_sync(0xffffffffu, cm1, 1));
        cm1 = fmaxf(cm1, __shfl_xor_sync(0xffffffffu, cm1, 2));
        float nm0 = fmaxf(m0, cm0), nm1 = fmaxf(m1, cm1);
        float sc0 = __expf(m0 - nm0), sc1 = __expf(m1 - nm1);
        l0 *= sc0; l1 *= sc1;
        #pragma unroll
        for (int nf = 0; nf < 8; nf++) {
            float p0 = __expf(sacc[nf][0] - nm0);
            float p1 = __expf(sacc[nf][1] - nm0);
            float p2 = __expf(sacc[nf][2] - nm1);
            float p3 = __expf(sacc[nf][3] - nm1);
            sacc[nf][0] = p0; sacc[nf][1] = p1;
            sacc[nf][2] = p2; sacc[nf][3] = p3;
            l0 += p0 + p1; l1 += p2 + p3;
            vacc[nf][0] *= sc0; vacc[nf][1] *= sc0;
            vacc[nf][2] *= sc1; vacc[nf][3] *= sc1;
        }
        m0 = nm0; m1 = nm1;

        // --- P fragments (C-layout -> A-layout is a pure pack) ---
        uint32_t pf[4][4];
        #pragma unroll
        for (int ks = 0; ks < 4; ks++) {
            pf[ks][0] = packbf(sacc[2*ks][0],     sacc[2*ks][1]);
            pf[ks][1] = packbf(sacc[2*ks][2],     sacc[2*ks][3]);
            pf[ks][2] = packbf(sacc[2*ks + 1][0], sacc[2*ks + 1][1]);
            pf[ks][3] = packbf(sacc[2*ks + 1][2], sacc[2*ks + 1][3]);
        }

        // --- AV accumulate: vacc += P V ---
        uint32_t vsb = smem_u32(&Vs[buf][0]);
        #pragma unroll
        for (int nfp = 0; nfp < 4; nfp++) {
            #pragma unroll
            for (int ks = 0; ks < 4; ks++) {
                uint32_t vf[4];
                uint32_t addr = vsb
                    + (uint32_t)(ks * 16 + lg8 * 8 + l7) * (AKST * 2)
                    + nfp * 32 + lg16 * 16;
                ldsm4t(vf, addr);
                mma16816(vacc[2*nfp],     pf[ks], vf);
                mma16816(vacc[2*nfp + 1], pf[ks], vf + 2);
            }
        }

        __syncthreads();
        if (c + 2 < NC) load_chunk(c + 2, buf);
    }

    // --- finalize: divide by row sums, write bf16 hi/lo pair ---
    l0 += __shfl_xor_sync(0xffffffffu, l0, 1);
    l0 += __shfl_xor_sync(0xffffffffu, l0, 2);
    l1 += __shfl_xor_sync(0xffffffffu, l1, 1);
    l1 += __shfl_xor_sync(0xffffffffu, l1, 2);
    float r0 = 1.0f / l0, r1 = 1.0f / l1;

    #pragma unroll
    for (int nf = 0; nf < 8; nf++) {
        int col = nf * 8 + q4 * 2;
        size_t o0 = base + (size_t)(q0 + lr) * DD + col;
        size_t o1 = base + (size_t)(q0 + lr + 8) * DD + col;
        float v00 = vacc[nf][0] * r0, v01 = vacc[nf][1] * r0;
        float v10 = vacc[nf][2] * r1, v11 = vacc[nf][3] * r1;
        bf16 h00 = __float2bfloat16(v00), h01 = __float2bfloat16(v01);
        bf16 h10 = __float2bfloat16(v10), h11 = __float2bfloat16(v11);
        bf16 e00 = __float2bfloat16(v00 - __bfloat162float(h00));
        bf16 e01 = __float2bfloat16(v01 - __bfloat162float(h01));
        bf16 e10 = __float2bfloat16(v10 - __bfloat162float(h10));
        bf16 e11 = __float2bfloat16(v11 - __bfloat162float(h11));
        *(__nv_bfloat162*)(avh + o0) = __nv_bfloat162(h00, h01);
        *(__nv_bfloat162*)(avh + o1) = __nv_bfloat162(h10, h11);
        *(__nv_bfloat162*)(avl + o0) = __nv_bfloat162(e00, e01);
        *(__nv_bfloat162*)(avl + o1) = __nv_bfloat162(e10, e11);
    }
}

// ---------------------------------------------------------------------------
// Driver
// ---------------------------------------------------------------------------
extern "C" void kernel_launch(void* const* d_in, const int* in_sizes, int n_in,
                              void* d_out, int out_size)
{
    const float* x      = (const float*)d_in[0];
    const int*   mask   = (const int*)  d_in[1];
    const float* wq     = (const float*)d_in[2];
    const float* wk     = (const float*)d_in[3];
    const float* wv     = (const float*)d_in[4];
    const float* wo     = (const float*)d_in[5];
    const float* w1     = (const float*)d_in[6];
    const float* b1     = (const float*)d_in[7];
    const float* w2     = (const float*)d_in[8];
    const float* b2     = (const float*)d_in[9];
    const float* alpha1 = (const float*)d_in[10];
    const float* bias1  = (const float*)d_in[11];
    const float* alpha2 = (const float*)d_in[12];
    const float* bias2  = (const float*)d_in[13];
    float* out = (float*)d_out;

    bf16 *xnh, *xnl, *qb, *kb, *vb, *avh, *avl, *xn2h, *xn2l, *hbh, *hbl;
    bf16 *wqh, *wql, *wkh, *wkl, *wvh, *wvl, *woh, *wol, *w1h, *w1l, *w2h, *w2l;
    float *x1;
    cudaGetSymbolAddress((void**)&xnh,  g_xnh);  cudaGetSymbolAddress((void**)&xnl,  g_xnl);
    cudaGetSymbolAddress((void**)&qb,   g_qb);   cudaGetSymbolAddress((void**)&kb,   g_kb);
    cudaGetSymbolAddress((void**)&vb,   g_vb);
    cudaGetSymbolAddress((void**)&avh,  g_avh);  cudaGetSymbolAddress((void**)&avl,  g_avl);
    cudaGetSymbolAddress((void**)&x1,   g_x1);
    cudaGetSymbolAddress((void**)&xn2h, g_xn2h); cudaGetSymbolAddress((void**)&xn2l, g_xn2l);
    cudaGetSymbolAddress((void**)&hbh,  g_hbh);  cudaGetSymbolAddress((void**)&hbl,  g_hbl);
    cudaGetSymbolAddress((void**)&wqh,  g_wqh);  cudaGetSymbolAddress((void**)&wql,  g_wql);
    cudaGetSymbolAddress((void**)&wkh,  g_wkh);  cudaGetSymbolAddress((void**)&wkl,  g_wkl);
    cudaGetSymbolAddress((void**)&wvh,  g_wvh);  cudaGetSymbolAddress((void**)&wvl,  g_wvl);
    cudaGetSymbolAddress((void**)&woh,  g_woh);  cudaGetSymbolAddress((void**)&wol,  g_wol);
    cudaGetSymbolAddress((void**)&w1h,  g_w1h);  cudaGetSymbolAddress((void**)&w1l,  g_w1l);
    cudaGetSymbolAddress((void**)&w2h,  g_w2h);  cudaGetSymbolAddress((void**)&w2l,  g_w2l);

    cudaFuncSetAttribute(gemm_mma<false,false,false,2>,
                         cudaFuncAttributeMaxDynamicSharedMemorySize, GEMM_SMEM);
    cudaFuncSetAttribute(gemm_mma<false,false,true,0>,
                         cudaFuncAttributeMaxDynamicSharedMemorySize, GEMM_SMEM);
    cudaFuncSetAttribute(gemm_mma<true,true,false,1>,
                         cudaFuncAttributeMaxDynamicSharedMemorySize, GEMM_SMEM);
    cudaFuncSetAttribute(gemm_mma<true,false,true,0>,
                         cudaFuncAttributeMaxDynamicSharedMemorySize, GEMM_SMEM);

    // 0. split weights to bf16 hi/lo
    split_k<<<(DD*DD/4 + 255)/256, 256>>>(wq, wqh, wql, DD*DD/4);
    split_k<<<(DD*DD/4 + 255)/256, 256>>>(wk, wkh, wkl, DD*DD/4);
    split_k<<<(DD*DD/4 + 255)/256, 256>>>(wv, wvh, wvl, DD*DD/4);
    split_k<<<(DD*DD/4 + 255)/256, 256>>>(wo, woh, wol, DD*DD/4);
    split_k<<<(DFFN*DD/4 + 255)/256, 256>>>(w1, w1h, w1l, DFFN*DD/4);
    split_k<<<(DD*DFFN/4 + 255)/256, 256>>>(w2, w2h, w2l, DD*DFFN/4);

    // 1. LN1 -> bf16 pair
    layernorm_k<<<NTOK, 256>>>(x, alpha1, bias1, xnh, xnl);

    // 2-4. Q, K, V projections (bf16 out)
    dim3 gProj(DD / 128, NTOK / 128);       // (8, 32)
    gemm_mma<false,false,false,2><<<gProj, 256, GEMM_SMEM>>>(
        xnh, xnl, wqh, wql, nullptr, nullptr, nullptr, qb, nullptr, NTOK, DD, DD);
    gemm_mma<false,false,false,2><<<gProj, 256, GEMM_SMEM>>>(
        xnh, xnl, wkh, wkl, nullptr, nullptr, nullptr, kb, nullptr, NTOK, DD, DD);
    gemm_mma<false,false,false,2><<<gProj, 256, GEMM_SMEM>>>(
        xnh, xnl, wvh, wvl, nullptr, nullptr, nullptr, vb, nullptr, NTOK, DD, DD);

    // 5. flash attention -> bf16 pair
    dim3 gAttn(SS / 128, BB * HH);          // (16, 32)
    fattn_k<<<gAttn, 256>>>(qb, kb, vb, mask, avh, avl);

    // 6. output projection + residual(x) -> x1 fp32
    gemm_mma<false,false,true,0><<<gProj, 256, GEMM_SMEM>>>(
        avh, avl, woh, wol, nullptr, x, x1, nullptr, nullptr, NTOK, DD, DD);

    // 7. LN2 -> bf16 pair
    layernorm_k<<<NTOK, 256>>>(x1, alpha2, bias2, xn2h, xn2l);

    // 8. FFN up: relu(xn2@w1^T + b1) -> bf16 pair
    dim3 gF1(DFFN / 128, NTOK / 128);       // (32, 32)
    gemm_mma<true,true,false,1><<<gF1, 256, GEMM_SMEM>>>(
        xn2h, xn2l, w1h, w1l, b1, nullptr, nullptr, hbh, hbl, NTOK, DFFN, DD);

    // 9. FFN down: h@w2^T + b2 + x1 -> out fp32
    gemm_mma<true,false,true,0><<<gProj, 256, GEMM_SMEM>>>(
        hbh, hbl, w2h, w2l, b2, x1, out, nullptr, nullptr, NTOK, DD, DFFN);
}

// round 6
// speedup vs baseline: 4.5031x; 1.0888x over previous
#include <cuda_runtime.h>
#include <cuda_bf16.h>
#include <math.h>
#include <stdint.h>

// Problem constants
#define BB 2
#define SS 2048
#define DD 1024
#define HH 16
#define DKK 64
#define DFFN 4096
#define NTOK (BB*SS)          // 4096
#define LN_EPS 1e-6f

typedef __nv_bfloat16 bf16;

// ---------------------------------------------------------------------------
// Scratch (static __device__ arrays: allocation-guard-safe)
// ---------------------------------------------------------------------------
__device__ bf16  g_xnh [(size_t)NTOK*DD],  g_xnl [(size_t)NTOK*DD];
__device__ bf16  g_qb  [(size_t)NTOK*DD];
__device__ bf16  g_kb  [(size_t)NTOK*DD];
__device__ bf16  g_vb  [(size_t)NTOK*DD];
__device__ bf16  g_avh [(size_t)NTOK*DD],  g_avl [(size_t)NTOK*DD];
__device__ float g_x1  [(size_t)NTOK*DD];
__device__ bf16  g_xn2h[(size_t)NTOK*DD],  g_xn2l[(size_t)NTOK*DD];
__device__ bf16  g_hbh [(size_t)NTOK*DFFN], g_hbl[(size_t)NTOK*DFFN];
__device__ bf16  g_wqh [(size_t)DD*DD];
__device__ bf16  g_wkh [(size_t)DD*DD];
__device__ bf16  g_wvh [(size_t)DD*DD];
__device__ bf16  g_woh [(size_t)DD*DD],   g_wol [(size_t)DD*DD];
__device__ bf16  g_w1h [(size_t)DFFN*DD], g_w1l [(size_t)DFFN*DD];
__device__ bf16  g_w2h [(size_t)DD*DFFN], g_w2l [(size_t)DD*DFFN];

// ---------------------------------------------------------------------------
// PTX helpers (cp.async + mma.sync + ldmatrix)
// ---------------------------------------------------------------------------
__device__ __forceinline__ uint32_t smem_u32(const void* p) {
    uint32_t a;
    asm("{ .reg .u64 t; cvta.to.shared.u64 t, %1; cvt.u32.u64 %0, t; }"
        : "=r"(a) : "l"(p));
    return a;
}
__device__ __forceinline__ void cp16(uint32_t d, const void* s) {
    asm volatile("cp.async.cg.shared.global [%0], [%1], 16;\n" :: "r"(d), "l"(s));
}
__device__ __forceinline__ void cp_commit() { asm volatile("cp.async.commit_group;\n" ::); }
template<int N> __device__ __forceinline__ void cp_wait() {
    asm volatile("cp.async.wait_group %0;\n" :: "n"(N));
}

__device__ __forceinline__ void mma16816(float* c, const uint32_t* a, const uint32_t* b) {
    asm volatile(
        "mma.sync.aligned.m16n8k16.row.col.f32.bf16.bf16.f32 "
        "{%0,%1,%2,%3}, {%4,%5,%6,%7}, {%8,%9}, {%0,%1,%2,%3};"
        : "+f"(c[0]), "+f"(c[1]), "+f"(c[2]), "+f"(c[3])
        : "r"(a[0]), "r"(a[1]), "r"(a[2]), "r"(a[3]), "r"(b[0]), "r"(b[1]));
}
__device__ __forceinline__ void ldsm4(uint32_t* r, uint32_t addr) {
    asm volatile("ldmatrix.sync.aligned.m8n8.x4.shared.b16 {%0,%1,%2,%3}, [%4];"
        : "=r"(r[0]), "=r"(r[1]), "=r"(r[2]), "=r"(r[3]) : "r"(addr));
}
__device__ __forceinline__ void ldsm4t(uint32_t* r, uint32_t addr) {
    asm volatile("ldmatrix.sync.aligned.m8n8.x4.trans.shared.b16 {%0,%1,%2,%3}, [%4];"
        : "=r"(r[0]), "=r"(r[1]), "=r"(r[2]), "=r"(r[3]) : "r"(addr));
}
__device__ __forceinline__ uint32_t packbf(float lo, float hi) {
    __nv_bfloat162 t = __floats2bfloat162_rn(lo, hi);
    return *(uint32_t*)&t;
}

// ---------------------------------------------------------------------------
// Reductions
// ---------------------------------------------------------------------------
__device__ __forceinline__ float warpReduceSum(float v) {
    #pragma unroll
    for (int o = 16; o > 0; o >>= 1) v += __shfl_xor_sync(0xffffffffu, v, o);
    return v;
}

// ---------------------------------------------------------------------------
// Split fp32 -> bf16 (hi, lo). n4 = n/4. (lo may be null -> hi only)
// ---------------------------------------------------------------------------
__global__ __launch_bounds__(256) void split_k(
    const float* __restrict__ w, bf16* __restrict__ hi,
    bf16* __restrict__ lo, int n4)
{
    int i = blockIdx.x * 256 + threadIdx.x;
    if (i >= n4) return;
    float4 v = ((const float4*)w)[i];
    bf16 h0 = __float2bfloat16(v.x), h1 = __float2bfloat16(v.y);
    bf16 h2 = __float2bfloat16(v.z), h3 = __float2bfloat16(v.w);
    __nv_bfloat162* hp = (__nv_bfloat162*)hi;
    hp[i*2]   = __nv_bfloat162(h0, h1);
    hp[i*2+1] = __nv_bfloat162(h2, h3);
    if (lo) {
        bf16 l0 = __float2bfloat16(v.x - __bfloat162float(h0));
        bf16 l1 = __float2bfloat16(v.y - __bfloat162float(h1));
        bf16 l2 = __float2bfloat16(v.z - __bfloat162float(h2));
        bf16 l3 = __float2bfloat16(v.w - __bfloat162float(h3));
        __nv_bfloat162* lp = (__nv_bfloat162*)lo;
        lp[i*2]   = __nv_bfloat162(l0, l1);
        lp[i*2+1] = __nv_bfloat162(l2, l3);
    }
}

// ---------------------------------------------------------------------------
// LayerNorm -> bf16 (hi, lo) pair. One 256-thread block per row of 1024.
// torch semantics: alpha * (x - mean) / (sqrt(var_unbiased) + eps) + bias
// ---------------------------------------------------------------------------
__global__ __launch_bounds__(256) void layernorm_k(
    const float* __restrict__ x, const float* __restrict__ alpha,
    const float* __restrict__ beta,
    bf16* __restrict__ oh, bf16* __restrict__ ol)
{
    int row = blockIdx.x;
    const float* xr = x + (size_t)row * DD;
    int i = threadIdx.x * 4;
    float4 xv = *(const float4*)(xr + i);
    float s  = xv.x + xv.y + xv.z + xv.w;
    float s2 = xv.x*xv.x + xv.y*xv.y + xv.z*xv.z + xv.w*xv.w;

    __shared__ float rs[8], rs2[8];
    __shared__ float smean, sinv;
    s  = warpReduceSum(s);
    s2 = warpReduceSum(s2);
    int w = threadIdx.x >> 5, l = threadIdx.x & 31;
    if (l == 0) { rs[w] = s; rs2[w] = s2; }
    __syncthreads();
    if (threadIdx.x == 0) {
        float S = 0.f, S2 = 0.f;
        #pragma unroll
        for (int k = 0; k < 8; k++) { S += rs[k]; S2 += rs2[k]; }
        float mean = S * (1.0f / (float)DD);
        float var  = (S2 - (float)DD * mean * mean) * (1.0f / (float)(DD - 1));
        var = fmaxf(var, 0.0f);
        smean = mean;
        sinv  = 1.0f / (sqrtf(var) + LN_EPS);
    }
    __syncthreads();
    float m = smean, inv = sinv;
    float4 av = *(const float4*)(alpha + i);
    float4 bv = *(const float4*)(beta  + i);
    float o0 = av.x * (xv.x - m) * inv + bv.x;
    float o1 = av.y * (xv.y - m) * inv + bv.y;
    float o2 = av.z * (xv.z - m) * inv + bv.z;
    float o3 = av.w * (xv.w - m) * inv + bv.w;
    bf16 h0 = __float2bfloat16(o0), h1 = __float2bfloat16(o1);
    bf16 h2 = __float2bfloat16(o2), h3 = __float2bfloat16(o3);
    bf16 l0 = __float2bfloat16(o0 - __bfloat162float(h0));
    bf16 l1 = __float2bfloat16(o1 - __bfloat162float(h1));
    bf16 l2 = __float2bfloat16(o2 - __bfloat162float(h2));
    bf16 l3 = __float2bfloat16(o3 - __bfloat162float(h3));
    size_t off = (size_t)row * DD + i;
    ((__nv_bfloat162*)(oh + off))[0] = __nv_bfloat162(h0, h1);
    ((__nv_bfloat162*)(oh + off))[1] = __nv_bfloat162(h2, h3);
    ((__nv_bfloat162*)(ol + off))[0] = __nv_bfloat162(l0, l1);
    ((__nv_bfloat162*)(ol + off))[1] = __nv_bfloat162(l2, l3);
}

// ---------------------------------------------------------------------------
// GEMM tiling constants (shared by split GEMM and QKV GEMM)
// 128x128 tile, BK=32, 256 threads (8 warps, 4x2; 32x64 per warp)
// ---------------------------------------------------------------------------
#define BK 32
#define LDSX 40                       // padded row stride in bf16 elems (80B)
#define MATB (128 * LDSX * 2)         // 10240 B per matrix tile
#define STAGE4 (4 * MATB)             // Ah, Al, Bh, Bl
#define GEMM_SMEM4 (2 * STAGE4)       // 81920 B
#define STAGE2 (2 * MATB)             // Ah, Bh
#define GEMM_SMEM2 (2 * STAGE2)       // 40960 B

// ldmatrix per-lane offsets (bytes, within a matrix tile):
//   A-frag: groups g: (g&1)->m-half, (g>>1)->k-half
//   B-frag: groups g: (g>>1)->n-half, (g&1)->k-half
__device__ __forceinline__ uint32_t a_ldsm_off(int lane) {
    int r = ((lane >> 3) & 1) * 8 + (lane & 7);
    int c = (lane >> 4) * 8;
    return (uint32_t)(r * LDSX + c) * 2;
}
__device__ __forceinline__ uint32_t b_ldsm_off(int lane) {
    int r = (lane >> 4) * 8 + (lane & 7);
    int c = ((lane >> 3) & 1) * 8;
    return (uint32_t)(r * LDSX + c) * 2;
}

// ---------------------------------------------------------------------------
// Split-bf16 GEMM: C = (Ah+Al) @ (Bh+Bl)^T via Ah*Bh + Ah*Bl + Al*Bh
// OUTM: 0=f32, 1=bf16 hi/lo pair
// ---------------------------------------------------------------------------
template<bool BIAS, bool RELU, bool RES, int OUTM>
__global__ __launch_bounds__(256) void gemm_mma(
    const bf16* __restrict__ Ah, const bf16* __restrict__ Al,
    const bf16* __restrict__ Bh, const bf16* __restrict__ Bl,
    const float* __restrict__ bias, const float* __restrict__ res,
    float* __restrict__ Cf, bf16* __restrict__ Ch, bf16* __restrict__ Cl,
    int M, int N, int K)
{
    extern __shared__ char sm_raw[];
    uint32_t sbase = smem_u32(sm_raw);

    int tid = threadIdx.x, lane = tid & 31, wid = tid >> 5;
    int m0 = blockIdx.y * 128, n0 = blockIdx.x * 128;
    int wm = wid & 3, wn = wid >> 2;
    int lr = lane >> 2, lk2 = (lane & 3) * 2;
    uint32_t aoff = a_ldsm_off(lane) + (uint32_t)(wm * 32) * (LDSX * 2);
    uint32_t boff = b_ldsm_off(lane) + (uint32_t)(wn * 64) * (LDSX * 2);

    float acc[2][8][4];
    #pragma unroll
    for (int a = 0; a < 2; a++)
        #pragma unroll
        for (int b = 0; b < 8; b++)
            #pragma unroll
            for (int c = 0; c < 4; c++) acc[a][b][c] = 0.f;

    const int NC = K / BK;

    auto load_chunk = [&](int c, int buf) {
        int kc = c * BK;
        uint32_t base = sbase + buf * STAGE4;
        #pragma unroll
        for (int T = 0; T < 4; T++) {
            const bf16* src = (T == 0) ? Ah : (T == 1) ? Al : (T == 2) ? Bh : Bl;
            int r0 = (T < 2) ? m0 : n0;
            uint32_t mb = base + T * MATB;
            #pragma unroll
            for (int i = 0; i < 2; i++) {
                int idx = tid + i * 256;
                int row = idx >> 2, c16 = idx & 3;
                cp16(mb + row * (LDSX * 2) + c16 * 16,
                     src + (size_t)(r0 + row) * K + kc + c16 * 8);
            }
        }
        cp_commit();
    };

    load_chunk(0, 0);
    if (NC > 1) load_chunk(1, 1);

    for (int c = 0; c < NC; c++) {
        if (c + 1 < NC) cp_wait<1>(); else cp_wait<0>();
        __syncthreads();

        uint32_t stg = sbase + (c & 1) * STAGE4;
        uint32_t sAh = stg + aoff;
        uint32_t sAl = stg + MATB + aoff;
        uint32_t sBh = stg + 2 * MATB + boff;
        uint32_t sBl = stg + 3 * MATB + boff;

        #pragma unroll
        for (int ks = 0; ks < 2; ks++) {
            uint32_t ah[2][4], al[2][4];
            #pragma unroll
            for (int mf = 0; mf < 2; mf++) {
                uint32_t ro = (uint32_t)(mf * 16) * (LDSX * 2) + ks * 32;
                ldsm4(ah[mf], sAh + ro);
                ldsm4(al[mf], sAl + ro);
            }
            #pragma unroll
            for (int nf2 = 0; nf2 < 4; nf2++) {
                uint32_t ro = (uint32_t)(nf2 * 16) * (LDSX * 2) + ks * 32;
                uint32_t bh[4], bl[4];
                ldsm4(bh, sBh + ro);
                ldsm4(bl, sBl + ro);
                #pragma unroll
                for (int mf = 0; mf < 2; mf++) {
                    mma16816(acc[mf][2*nf2],     ah[mf], bh);
                    mma16816(acc[mf][2*nf2],     ah[mf], bl);
                    mma16816(acc[mf][2*nf2],     al[mf], bh);
                    mma16816(acc[mf][2*nf2 + 1], ah[mf], bh + 2);
                    mma16816(acc[mf][2*nf2 + 1], ah[mf], bl + 2);
                    mma16816(acc[mf][2*nf2 + 1], al[mf], bh + 2);
                }
            }
        }
        __syncthreads();
        if (c + 2 < NC) load_chunk(c + 2, c & 1);
    }

    // epilogue
    #pragma unroll
    for (int mf = 0; mf < 2; mf++) {
        int r0 = m0 + wm * 32 + mf * 16 + lr;
        #pragma unroll
        for (int nf = 0; nf < 8; nf++) {
            int col = n0 + wn * 64 + nf * 8 + lk2;
            float* cc = acc[mf][nf];
            float v00 = cc[0], v01 = cc[1], v10 = cc[2], v11 = cc[3];
            if (BIAS) {
                float b0 = __ldg(bias + col), b1 = __ldg(bias + col + 1);
                v00 += b0; v01 += b1; v10 += b0; v11 += b1;
            }
            if (RELU) {
                v00 = fmaxf(v00, 0.f); v01 = fmaxf(v01, 0.f);
                v10 = fmaxf(v10, 0.f); v11 = fmaxf(v11, 0.f);
            }
            if (RES) {
                float2 ra = *(const float2*)(res + (size_t)r0 * N + col);
                float2 rb = *(const float2*)(res + (size_t)(r0 + 8) * N + col);
                v00 += ra.x; v01 += ra.y; v10 += rb.x; v11 += rb.y;
            }
            if (OUTM == 1) {
                bf16 h00 = __float2bfloat16(v00), h01 = __float2bfloat16(v01);
                bf16 h10 = __float2bfloat16(v10), h11 = __float2bfloat16(v11);
                bf16 l00 = __float2bfloat16(v00 - __bfloat162float(h00));
                bf16 l01 = __float2bfloat16(v01 - __bfloat162float(h01));
                bf16 l10 = __float2bfloat16(v10 - __bfloat162float(h10));
                bf16 l11 = __float2bfloat16(v11 - __bfloat162float(h11));
                *(__nv_bfloat162*)(Ch + (size_t)r0 * N + col)       = __nv_bfloat162(h00, h01);
                *(__nv_bfloat162*)(Ch + (size_t)(r0 + 8) * N + col) = __nv_bfloat162(h10, h11);
                *(__nv_bfloat162*)(Cl + (size_t)r0 * N + col)       = __nv_bfloat162(l00, l01);
                *(__nv_bfloat162*)(Cl + (size_t)(r0 + 8) * N + col) = __nv_bfloat162(l10, l11);
            } else {
                *(float2*)(Cf + (size_t)r0 * N + col)       = make_float2(v00, v01);
                *(float2*)(Cf + (size_t)(r0 + 8) * N + col) = make_float2(v10, v11);
            }
        }
    }
}

// ---------------------------------------------------------------------------
// Fused QKV GEMM (single bf16 product): grid.x = 3*8; which = bx>>3 selects
// weight/output. C_sel = A @ Bsel^T, bf16 out.
// ---------------------------------------------------------------------------
__global__ __launch_bounds__(256) void gemm_qkv(
    const bf16* __restrict__ A,
    const bf16* __restrict__ B0, const bf16* __restrict__ B1,
    const bf16* __restrict__ B2,
    bf16* __restrict__ C0, bf16* __restrict__ C1, bf16* __restrict__ C2)
{
    extern __shared__ char sm_raw[];
    uint32_t sbase = smem_u32(sm_raw);
    const int K = DD, N = DD;

    int which = blockIdx.x >> 3;
    const bf16* Bw = (which == 0) ? B0 : (which == 1) ? B1 : B2;
    bf16* Cw = (which == 0) ? C0 : (which == 1) ? C1 : C2;

    int tid = threadIdx.x, lane = tid & 31, wid = tid >> 5;
    int m0 = blockIdx.y * 128, n0 = (blockIdx.x & 7) * 128;
    int wm = wid & 3, wn = wid >> 2;
    int lr = lane >> 2, lk2 = (lane & 3) * 2;
    uint32_t aoff = a_ldsm_off(lane) + (uint32_t)(wm * 32) * (LDSX * 2);
    uint32_t boff = b_ldsm_off(lane) + (uint32_t)(wn * 64) * (LDSX * 2);

    float acc[2][8][4];
    #pragma unroll
    for (int a = 0; a < 2; a++)
        #pragma unroll
        for (int b = 0; b < 8; b++)
            #pragma unroll
            for (int c = 0; c < 4; c++) acc[a][b][c] = 0.f;

    const int NC = K / BK;

    auto load_chunk = [&](int c, int buf) {
        int kc = c * BK;
        uint32_t base = sbase + buf * STAGE2;
        #pragma unroll
        for (int T = 0; T < 2; T++) {
            const bf16* src = (T == 0) ? A : Bw;
            int r0 = (T == 0) ? m0 : n0;
            uint32_t mb = base + T * MATB;
            int row = tid >> 1, c16 = tid & 1;
            cp16(mb + row * (LDSX * 2) + c16 * 32,
                 src + (size_t)(r0 + row) * K + kc + c16 * 16);
            cp16(mb + row * (LDSX * 2) + c16 * 32 + 16,
                 src + (size_t)(r0 + row) * K + kc + c16 * 16 + 8);
        }
        cp_commit();
    };

    load_chunk(0, 0);
    if (NC > 1) load_chunk(1, 1);

    for (int c = 0; c < NC; c++) {
        if (c + 1 < NC) cp_wait<1>(); else cp_wait<0>();
        __syncthreads();

        uint32_t stg = sbase + (c & 1) * STAGE2;
        uint32_t sA = stg + aoff;
        uint32_t sB = stg + MATB + boff;

        #pragma unroll
        for (int ks = 0; ks < 2; ks++) {
            uint32_t ah[2][4];
            #pragma unroll
            for (int mf = 0; mf < 2; mf++)
                ldsm4(ah[mf], sA + (uint32_t)(mf * 16) * (LDSX * 2) + ks * 32);
            #pragma unroll
            for (int nf2 = 0; nf2 < 4; nf2++) {
                uint32_t bh[4];
                ldsm4(bh, sB + (uint32_t)(nf2 * 16) * (LDSX * 2) + ks * 32);
                #pragma unroll
                for (int mf = 0; mf < 2; mf++) {
                    mma16816(acc[mf][2*nf2],     ah[mf], bh);
                    mma16816(acc[mf][2*nf2 + 1], ah[mf], bh + 2);
                }
            }
        }
        __syncthreads();
        if (c + 2 < NC) load_chunk(c + 2, c & 1);
    }

    #pragma unroll
    for (int mf = 0; mf < 2; mf++) {
        int r0 = m0 + wm * 32 + mf * 16 + lr;
        #pragma unroll
        for (int nf = 0; nf < 8; nf++) {
            int col = n0 + wn * 64 + nf * 8 + lk2;
            float* cc = acc[mf][nf];
            *(__nv_bfloat162*)(Cw + (size_t)r0 * N + col) =
                __floats2bfloat162_rn(cc[0], cc[1]);
            *(__nv_bfloat162*)(Cw + (size_t)(r0 + 8) * N + col) =
                __floats2bfloat162_rn(cc[2], cc[3]);
        }
    }
}

// ---------------------------------------------------------------------------
// Flash attention (bf16 mma.sync): one CTA per (b, h, 128-query tile).
// 8 warps x 16 Q rows. K/V chunks of 64 keys, cp.async double-buffered.
// Online softmax in registers. Output: bf16 (hi,lo) pair.
// ---------------------------------------------------------------------------
#define AKST 72                       // smem row stride in bf16 (144 B)

__global__ __launch_bounds__(256) void fattn_k(
    const bf16* __restrict__ qg, const bf16* __restrict__ kg,
    const bf16* __restrict__ vg, const int* __restrict__ mask,
    bf16* __restrict__ avh, bf16* __restrict__ avl)
{
    __shared__ __align__(16) bf16 Ks[2][64 * AKST];
    __shared__ __align__(16) bf16 Vs[2][64 * AKST];
    __shared__ __align__(16) int  Msk[2][64];

    int t = threadIdx.x, lane = t & 31, w = t >> 5;
    int h = blockIdx.y & (HH - 1), b = blockIdx.y >> 4;
    size_t base = (size_t)b * SS * DD + h * DKK;
    int q0 = blockIdx.x * 128 + w * 16;
    int lr = lane >> 2, q4 = lane & 3;
    int l7 = lane & 7, lg8 = (lane >> 3) & 1, lg16 = (lane >> 4) & 1;

    uint32_t qf[4][4];
    #pragma unroll
    for (int ks = 0; ks < 4; ks++) {
        int col = ks * 16 + q4 * 2;
        qf[ks][0] = *(const uint32_t*)(qg + base + (size_t)(q0 + lr) * DD + col);
        qf[ks][1] = *(const uint32_t*)(qg + base + (size_t)(q0 + lr + 8) * DD + col);
        qf[ks][2] = *(const uint32_t*)(qg + base + (size_t)(q0 + lr) * DD + col + 8);
        qf[ks][3] = *(const uint32_t*)(qg + base + (size_t)(q0 + lr + 8) * DD + col + 8);
    }

    float vacc[8][4];
    #pragma unroll
    for (int nf = 0; nf < 8; nf++)
        #pragma unroll
        for (int c = 0; c < 4; c++) vacc[nf][c] = 0.f;
    float m0 = -1e30f, m1 = -1e30f, l0 = 0.f, l1 = 0.f;

    const int NC = SS / 64;

    auto load_chunk = [&](int c, int buf) {
        int key0 = c * 64;
        uint32_t kbAddr = smem_u32(&Ks[buf][0]);
        uint32_t vbAddr = smem_u32(&Vs[buf][0]);
        #pragma unroll
        for (int i = 0; i < 2; i++) {
            int idx = t * 2 + i;
            int row = idx >> 3, seg = idx & 7;
            cp16(kbAddr + row * (AKST * 2) + seg * 16,
                 kg + base + (size_t)(key0 + row) * DD + seg * 8);
            cp16(vbAddr + row * (AKST * 2) + seg * 16,
                 vg + base + (size_t)(key0 + row) * DD + seg * 8);
        }
        if (t < 16)
            cp16(smem_u32(&Msk[buf][0]) + t * 16, mask + b * SS + key0 + t * 4);
        cp_commit();
    };

    load_chunk(0, 0);
    load_chunk(1, 1);

    for (int c = 0; c < NC; c++) {
        if (c + 1 < NC) cp_wait<1>(); else cp_wait<0>();
        __syncthreads();
        int buf = c & 1;

        float sacc[8][4];
        #pragma unroll
        for (int nf = 0; nf < 8; nf++)
            #pragma unroll
            for (int cc = 0; cc < 4; cc++) sacc[nf][cc] = 0.f;

        uint32_t ksb = smem_u32(&Ks[buf][0]);
        #pragma unroll
        for (int ks = 0; ks < 4; ks++) {
            #pragma unroll
            for (int nfp = 0; nfp < 4; nfp++) {
                uint32_t kf[4];
                uint32_t addr = ksb
                    + (uint32_t)(nfp * 16 + lg16 * 8 + l7) * (AKST * 2)
                    + ks * 32 + lg8 * 16;
                ldsm4(kf, addr);
                mma16816(sacc[2*nfp],     qf[ks], kf);
                mma16816(sacc[2*nfp + 1], qf[ks], kf + 2);
            }
        }

        #pragma unroll
        for (int nf = 0; nf < 8; nf++) {
            int col = nf * 8 + q4 * 2;
            int mk0 = Msk[buf][col], mk1 = Msk[buf][col + 1];
            float s0 = sacc[nf][0] * 0.125f, s1 = sacc[nf][1] * 0.125f;
            float s2 = sacc[nf][2] * 0.125f, s3 = sacc[nf][3] * 0.125f;
            sacc[nf][0] = mk0 ? s0 : -1e9f;
            sacc[nf][1] = mk1 ? s1 : -1e9f;
            sacc[nf][2] = mk0 ? s2 : -1e9f;
            sacc[nf][3] = mk1 ? s3 : -1e9f;
        }

        float cm0 = -1e30f, cm1 = -1e30f;
        #pragma unroll
        for (int nf = 0; nf < 8; nf++) {
            cm0 = fmaxf(cm0, fmaxf(sacc[nf][0], sacc[nf][1]));
            cm1 = fmaxf(cm1, fmaxf(sacc[nf][2], sacc[nf][3]));
        }
        cm0 = fmaxf(cm0, __shfl_xor_sync(0xffffffffu, cm0, 1));
        cm0 = fmaxf(cm0, __shfl_xor_sync(0xffffffffu, cm0, 2));
        cm1 = fmaxf(cm1, __shfl_xor_sync(0xffffffffu, cm1, 1));
        cm1 = fmaxf(cm1, __shfl_xor_sync(0xffffffffu, cm1, 2));
        float nm0 = fmaxf(m0, cm0), nm1 = fmaxf(m1, cm1);
        float sc0 = __expf(m0 - nm0), sc1 = __expf(m1 - nm1);
        l0 *= sc0; l1 *= sc1;
        #pragma unroll
        for (int nf = 0; nf < 8; nf++) {
            float p0 = __expf(sacc[nf][0] - nm0);
            float p1 = __expf(sacc[nf][1] - nm0);
            float p2 = __expf(sacc[nf][2] - nm1);
            float p3 = __expf(sacc[nf][3] - nm1);
            sacc[nf][0] = p0; sacc[nf][1] = p1;
            sacc[nf][2] = p2; sacc[nf][3] = p3;
            l0 += p0 + p1; l1 += p2 + p3;
            vacc[nf][0] *= sc0; vacc[nf][1] *= sc0;
            vacc[nf][2] *= sc1; vacc[nf][3] *= sc1;
        }
        m0 = nm0; m1 = nm1;

        uint32_t pf[4][4];
        #pragma unroll
        for (int ks = 0; ks < 4; ks++) {
            pf[ks][0] = packbf(sacc[2*ks][0],     sacc[2*ks][1]);
            pf[ks][1] = packbf(sacc[2*ks][2],     sacc[2*ks][3]);
            pf[ks][2] = packbf(sacc[2*ks + 1][0], sacc[2*ks + 1][1]);
            pf[ks][3] = packbf(sacc[2*ks + 1][2], sacc[2*ks + 1][3]);
        }

        uint32_t vsb = smem_u32(&Vs[buf][0]);
        #pragma unroll
        for (int nfp = 0; nfp < 4; nfp++) {
            #pragma unroll
            for (int ks = 0; ks < 4; ks++) {
                uint32_t vf[4];
                uint32_t addr = vsb
                    + (uint32_t)(ks * 16 + lg8 * 8 + l7) * (AKST * 2)
                    + nfp * 32 + lg16 * 16;
                ldsm4t(vf, addr);
                mma16816(vacc[2*nfp],     pf[ks], vf);
                mma16816(vacc[2*nfp + 1], pf[ks], vf + 2);
            }
        }

        __syncthreads();
        if (c + 2 < NC) load_chunk(c + 2, buf);
    }

    l0 += __shfl_xor_sync(0xffffffffu, l0, 1);
    l0 += __shfl_xor_sync(0xffffffffu, l0, 2);
    l1 += __shfl_xor_sync(0xffffffffu, l1, 1);
    l1 += __shfl_xor_sync(0xffffffffu, l1, 2);
    float r0 = 1.0f / l0, r1 = 1.0f / l1;

    #pragma unroll
    for (int nf = 0; nf < 8; nf++) {
        int col = nf * 8 + q4 * 2;
        size_t o0 = base + (size_t)(q0 + lr) * DD + col;
        size_t o1 = base + (size_t)(q0 + lr + 8) * DD + col;
        float v00 = vacc[nf][0] * r0, v01 = vacc[nf][1] * r0;
        float v10 = vacc[nf][2] * r1, v11 = vacc[nf][3] * r1;
        bf16 h00 = __float2bfloat16(v00), h01 = __float2bfloat16(v01);
        bf16 h10 = __float2bfloat16(v10), h11 = __float2bfloat16(v11);
        bf16 e00 = __float2bfloat16(v00 - __bfloat162float(h00));
        bf16 e01 = __float2bfloat16(v01 - __bfloat162float(h01));
        bf16 e10 = __float2bfloat16(v10 - __bfloat162float(h10));
        bf16 e11 = __float2bfloat16(v11 - __bfloat162float(h11));
        *(__nv_bfloat162*)(avh + o0) = __nv_bfloat162(h00, h01);
        *(__nv_bfloat162*)(avh + o1) = __nv_bfloat162(h10, h11);
        *(__nv_bfloat162*)(avl + o0) = __nv_bfloat162(e00, e01);
        *(__nv_bfloat162*)(avl + o1) = __nv_bfloat162(e10, e11);
    }
}

// ---------------------------------------------------------------------------
// Driver
// ---------------------------------------------------------------------------
extern "C" void kernel_launch(void* const* d_in, const int* in_sizes, int n_in,
                              void* d_out, int out_size)
{
    const float* x      = (const float*)d_in[0];
    const int*   mask   = (const int*)  d_in[1];
    const float* wq     = (const float*)d_in[2];
    const float* wk     = (const float*)d_in[3];
    const float* wv     = (const float*)d_in[4];
    const float* wo     = (const float*)d_in[5];
    const float* w1     = (const float*)d_in[6];
    const float* b1     = (const float*)d_in[7];
    const float* w2     = (const float*)d_in[8];
    const float* b2     = (const float*)d_in[9];
    const float* alpha1 = (const float*)d_in[10];
    const float* bias1  = (const float*)d_in[11];
    const float* alpha2 = (const float*)d_in[12];
    const float* bias2  = (const float*)d_in[13];
    float* out = (float*)d_out;

    bf16 *xnh, *xnl, *qb, *kb, *vb, *avh, *avl, *xn2h, *xn2l, *hbh, *hbl;
    bf16 *wqh, *wkh, *wvh, *woh, *wol, *w1h, *w1l, *w2h, *w2l;
    float *x1;
    cudaGetSymbolAddress((void**)&xnh,  g_xnh);  cudaGetSymbolAddress((void**)&xnl,  g_xnl);
    cudaGetSymbolAddress((void**)&qb,   g_qb);   cudaGetSymbolAddress((void**)&kb,   g_kb);
    cudaGetSymbolAddress((void**)&vb,   g_vb);
    cudaGetSymbolAddress((void**)&avh,  g_avh);  cudaGetSymbolAddress((void**)&avl,  g_avl);
    cudaGetSymbolAddress((void**)&x1,   g_x1);
    cudaGetSymbolAddress((void**)&xn2h, g_xn2h); cudaGetSymbolAddress((void**)&xn2l, g_xn2l);
    cudaGetSymbolAddress((void**)&hbh,  g_hbh);  cudaGetSymbolAddress((void**)&hbl,  g_hbl);
    cudaGetSymbolAddress((void**)&wqh,  g_wqh);
    cudaGetSymbolAddress((void**)&wkh,  g_wkh);
    cudaGetSymbolAddress((void**)&wvh,  g_wvh);
    cudaGetSymbolAddress((void**)&woh,  g_woh);  cudaGetSymbolAddress((void**)&wol,  g_wol);
    cudaGetSymbolAddress((void**)&w1h,  g_w1h);  cudaGetSymbolAddress((void**)&w1l,  g_w1l);
    cudaGetSymbolAddress((void**)&w2h,  g_w2h);  cudaGetSymbolAddress((void**)&w2l,  g_w2l);

    cudaFuncSetAttribute(gemm_mma<false,false,true,0>,
                         cudaFuncAttributeMaxDynamicSharedMemorySize, GEMM_SMEM4);
    cudaFuncSetAttribute(gemm_mma<true,true,false,1>,
                         cudaFuncAttributeMaxDynamicSharedMemorySize, GEMM_SMEM4);
    cudaFuncSetAttribute(gemm_mma<true,false,true,0>,
                         cudaFuncAttributeMaxDynamicSharedMemorySize, GEMM_SMEM4);
    cudaFuncSetAttribute(gemm_qkv,
                         cudaFuncAttributeMaxDynamicSharedMemorySize, GEMM_SMEM2);

    // 0. weights -> bf16 (hi only for QKV; hi/lo for wo, w1, w2)
    split_k<<<(DD*DD/4 + 255)/256, 256>>>(wq, wqh, nullptr, DD*DD/4);
    split_k<<<(DD*DD/4 + 255)/256, 256>>>(wk, wkh, nullptr, DD*DD/4);
    split_k<<<(DD*DD/4 + 255)/256, 256>>>(wv, wvh, nullptr, DD*DD/4);
    split_k<<<(DD*DD/4 + 255)/256, 256>>>(wo, woh, wol, DD*DD/4);
    split_k<<<(DFFN*DD/4 + 255)/256, 256>>>(w1, w1h, w1l, DFFN*DD/4);
    split_k<<<(DD*DFFN/4 + 255)/256, 256>>>(w2, w2h, w2l, DD*DFFN/4);

    // 1. LN1 -> bf16 pair
    layernorm_k<<<NTOK, 256>>>(x, alpha1, bias1, xnh, xnl);

    // 2. fused Q/K/V projections (single bf16 product)
    dim3 gQKV(3 * (DD / 128), NTOK / 128);  // (24, 32)
    gemm_qkv<<<gQKV, 256, GEMM_SMEM2>>>(xnh, wqh, wkh, wvh, qb, kb, vb);

    // 3. flash attention -> bf16 pair
    dim3 gAttn(SS / 128, BB * HH);          // (16, 32)
    fattn_k<<<gAttn, 256>>>(qb, kb, vb, mask, avh, avl);

    // 4. output projection + residual(x) -> x1 fp32
    dim3 gProj(DD / 128, NTOK / 128);       // (8, 32)
    gemm_mma<false,false,true,0><<<gProj, 256, GEMM_SMEM4>>>(
        avh, avl, woh, wol, nullptr, x, x1, nullptr, nullptr, NTOK, DD, DD);

    // 5. LN2 -> bf16 pair
    layernorm_k<<<NTOK, 256>>>(x1, alpha2, bias2, xn2h, xn2l);

    // 6. FFN up: relu(xn2@w1^T + b1) -> bf16 pair
    dim3 gF1(DFFN / 128, NTOK / 128);       // (32, 32)
    gemm_mma<true,true,false,1><<<gF1, 256, GEMM_SMEM4>>>(
        xn2h, xn2l, w1h, w1l, b1, nullptr, nullptr, hbh, hbl, NTOK, DFFN, DD);

    // 7. FFN down: h@w2^T + b2 + x1 -> out fp32
    gemm_mma<true,false,true,0><<<gProj, 256, GEMM_SMEM4>>>(
        hbh, hbl, w2h, w2l, b2, x1, out, nullptr, nullptr, NTOK, DD, DFFN);
}

// round 7
// speedup vs baseline: 7.5333x; 1.6729x over previous
#include <cuda_runtime.h>
#include <cuda_fp16.h>
#include <math.h>
#include <stdint.h>

// Problem constants
#define BB 2
#define SS 2048
#define DD 1024
#define HH 16
#define DKK 64
#define DFFN 4096
#define NTOK (BB*SS)          // 4096
#define LN_EPS 1e-6f

typedef __half h16;

// ---------------------------------------------------------------------------
// Scratch (static __device__ arrays: allocation-guard-safe)
// ---------------------------------------------------------------------------
__device__ h16   g_xn  [(size_t)NTOK*DD];
__device__ h16   g_qb  [(size_t)NTOK*DD];
__device__ h16   g_kb  [(size_t)NTOK*DD];
__device__ h16   g_vb  [(size_t)NTOK*DD];
__device__ h16   g_av  [(size_t)NTOK*DD];
__device__ float g_x1  [(size_t)NTOK*DD];
__device__ h16   g_xn2 [(size_t)NTOK*DD];
__device__ h16   g_hb  [(size_t)NTOK*DFFN];
__device__ h16   g_wqh [(size_t)DD*DD];
__device__ h16   g_wkh [(size_t)DD*DD];
__device__ h16   g_wvh [(size_t)DD*DD];
__device__ h16   g_woh [(size_t)DD*DD];
__device__ h16   g_w1h [(size_t)DFFN*DD];
__device__ h16   g_w2h [(size_t)DD*DFFN];

// ---------------------------------------------------------------------------
// PTX helpers (cp.async + mma.sync + ldmatrix)
// ---------------------------------------------------------------------------
__device__ __forceinline__ uint32_t smem_u32(const void* p) {
    uint32_t a;
    asm("{ .reg .u64 t; cvta.to.shared.u64 t, %1; cvt.u32.u64 %0, t; }"
        : "=r"(a) : "l"(p));
    return a;
}
__device__ __forceinline__ void cp16(uint32_t d, const void* s) {
    asm volatile("cp.async.cg.shared.global [%0], [%1], 16;\n" :: "r"(d), "l"(s));
}
__device__ __forceinline__ void cp_commit() { asm volatile("cp.async.commit_group;\n" ::); }
template<int N> __device__ __forceinline__ void cp_wait() {
    asm volatile("cp.async.wait_group %0;\n" :: "n"(N));
}

__device__ __forceinline__ void mma16816(float* c, const uint32_t* a, const uint32_t* b) {
    asm volatile(
        "mma.sync.aligned.m16n8k16.row.col.f32.f16.f16.f32 "
        "{%0,%1,%2,%3}, {%4,%5,%6,%7}, {%8,%9}, {%0,%1,%2,%3};"
        : "+f"(c[0]), "+f"(c[1]), "+f"(c[2]), "+f"(c[3])
        : "r"(a[0]), "r"(a[1]), "r"(a[2]), "r"(a[3]), "r"(b[0]), "r"(b[1]));
}
__device__ __forceinline__ void ldsm4(uint32_t* r, uint32_t addr) {
    asm volatile("ldmatrix.sync.aligned.m8n8.x4.shared.b16 {%0,%1,%2,%3}, [%4];"
        : "=r"(r[0]), "=r"(r[1]), "=r"(r[2]), "=r"(r[3]) : "r"(addr));
}
__device__ __forceinline__ void ldsm4t(uint32_t* r, uint32_t addr) {
    asm volatile("ldmatrix.sync.aligned.m8n8.x4.trans.shared.b16 {%0,%1,%2,%3}, [%4];"
        : "=r"(r[0]), "=r"(r[1]), "=r"(r[2]), "=r"(r[3]) : "r"(addr));
}
__device__ __forceinline__ uint32_t packh(float lo, float hi) {
    __half2 t = __floats2half2_rn(lo, hi);
    return *(uint32_t*)&t;
}

// ---------------------------------------------------------------------------
// Reductions
// ---------------------------------------------------------------------------
__device__ __forceinline__ float warpReduceSum(float v) {
    #pragma unroll
    for (int o = 16; o > 0; o >>= 1) v += __shfl_xor_sync(0xffffffffu, v, o);
    return v;
}

// ---------------------------------------------------------------------------
// Convert fp32 -> fp16. n4 = n/4.
// ---------------------------------------------------------------------------
__global__ __launch_bounds__(256) void cvt_k(
    const float* __restrict__ w, h16* __restrict__ o, int n4)
{
    int i = blockIdx.x * 256 + threadIdx.x;
    if (i >= n4) return;
    float4 v = ((const float4*)w)[i];
    __half2* op = (__half2*)o;
    op[i*2]   = __floats2half2_rn(v.x, v.y);
    op[i*2+1] = __floats2half2_rn(v.z, v.w);
}

// ---------------------------------------------------------------------------
// LayerNorm -> fp16. One 256-thread block per row of 1024.
// torch semantics: alpha * (x - mean) / (sqrt(var_unbiased) + eps) + bias
// ---------------------------------------------------------------------------
__global__ __launch_bounds__(256) void layernorm_k(
    const float* __restrict__ x, const float* __restrict__ alpha,
    const float* __restrict__ beta, h16* __restrict__ oh)
{
    int row = blockIdx.x;
    const float* xr = x + (size_t)row * DD;
    int i = threadIdx.x * 4;
    float4 xv = *(const float4*)(xr + i);
    float s  = xv.x + xv.y + xv.z + xv.w;
    float s2 = xv.x*xv.x + xv.y*xv.y + xv.z*xv.z + xv.w*xv.w;

    __shared__ float rs[8], rs2[8];
    __shared__ float smean, sinv;
    s  = warpReduceSum(s);
    s2 = warpReduceSum(s2);
    int w = threadIdx.x >> 5, l = threadIdx.x & 31;
    if (l == 0) { rs[w] = s; rs2[w] = s2; }
    __syncthreads();
    if (threadIdx.x == 0) {
        float S = 0.f, S2 = 0.f;
        #pragma unroll
        for (int k = 0; k < 8; k++) { S += rs[k]; S2 += rs2[k]; }
        float mean = S * (1.0f / (float)DD);
        float var  = (S2 - (float)DD * mean * mean) * (1.0f / (float)(DD - 1));
        var = fmaxf(var, 0.0f);
        smean = mean;
        sinv  = 1.0f / (sqrtf(var) + LN_EPS);
    }
    __syncthreads();
    float m = smean, inv = sinv;
    float4 av = *(const float4*)(alpha + i);
    float4 bv = *(const float4*)(beta  + i);
    float o0 = av.x * (xv.x - m) * inv + bv.x;
    float o1 = av.y * (xv.y - m) * inv + bv.y;
    float o2 = av.z * (xv.z - m) * inv + bv.z;
    float o3 = av.w * (xv.w - m) * inv + bv.w;
    size_t off = (size_t)row * DD + i;
    ((__half2*)(oh + off))[0] = __floats2half2_rn(o0, o1);
    ((__half2*)(oh + off))[1] = __floats2half2_rn(o2, o3);
}

// ---------------------------------------------------------------------------
// GEMM tiling: 128x128 tile, BK=32, 256 threads (8 warps 4x2; 32x64/warp),
// single fp16 product, double-buffered cp.async.
// ---------------------------------------------------------------------------
#define BK 32
#define LDSX 40                       // padded row stride in h16 elems (80B)
#define MATB (128 * LDSX * 2)         // 10240 B per matrix tile
#define STAGE (2 * MATB)              // A, B
#define GEMM_SMEM (2 * STAGE)         // 40960 B

__device__ __forceinline__ uint32_t a_ldsm_off(int lane) {
    int r = ((lane >> 3) & 1) * 8 + (lane & 7);
    int c = (lane >> 4) * 8;
    return (uint32_t)(r * LDSX + c) * 2;
}
__device__ __forceinline__ uint32_t b_ldsm_off(int lane) {
    int r = (lane >> 4) * 8 + (lane & 7);
    int c = ((lane >> 3) & 1) * 8;
    return (uint32_t)(r * LDSX + c) * 2;
}

// Core inner GEMM: accumulates A(m0..m0+128) @ B(n0..n0+128)^T over K.
template<bool BIAS, bool RELU, bool RES, bool OUTH>
__device__ __forceinline__ void gemm_body(
    const h16* __restrict__ A, const h16* __restrict__ B,
    const float* __restrict__ bias, const float* __restrict__ res,
    float* __restrict__ Cf, h16* __restrict__ Ch,
    int m0, int n0, int N, int K, uint32_t sbase)
{
    int tid = threadIdx.x, lane = tid & 31, wid = tid >> 5;
    int wm = wid & 3, wn = wid >> 2;
    int lr = lane >> 2, lk2 = (lane & 3) * 2;
    uint32_t aoff = a_ldsm_off(lane) + (uint32_t)(wm * 32) * (LDSX * 2);
    uint32_t boff = b_ldsm_off(lane) + (uint32_t)(wn * 64) * (LDSX * 2);

    float acc[2][8][4];
    #pragma unroll
    for (int a = 0; a < 2; a++)
        #pragma unroll
        for (int b = 0; b < 8; b++)
            #pragma unroll
            for (int c = 0; c < 4; c++) acc[a][b][c] = 0.f;

    const int NC = K / BK;

    auto load_chunk = [&](int c, int buf) {
        int kc = c * BK;
        uint32_t base = sbase + buf * STAGE;
        #pragma unroll
        for (int T = 0; T < 2; T++) {
            const h16* src = (T == 0) ? A : B;
            int r0 = (T == 0) ? m0 : n0;
            uint32_t mb = base + T * MATB;
            int row = tid >> 1, c16 = tid & 1;
            cp16(mb + row * (LDSX * 2) + c16 * 32,
                 src + (size_t)(r0 + row) * K + kc + c16 * 16);
            cp16(mb + row * (LDSX * 2) + c16 * 32 + 16,
                 src + (size_t)(r0 + row) * K + kc + c16 * 16 + 8);
        }
        cp_commit();
    };

    load_chunk(0, 0);
    if (NC > 1) load_chunk(1, 1);

    for (int c = 0; c < NC; c++) {
        if (c + 1 < NC) cp_wait<1>(); else cp_wait<0>();
        __syncthreads();

        uint32_t stg = sbase + (c & 1) * STAGE;
        uint32_t sA = stg + aoff;
        uint32_t sB = stg + MATB + boff;

        #pragma unroll
        for (int ks = 0; ks < 2; ks++) {
            uint32_t ah[2][4];
            #pragma unroll
            for (int mf = 0; mf < 2; mf++)
                ldsm4(ah[mf], sA + (uint32_t)(mf * 16) * (LDSX * 2) + ks * 32);
            #pragma unroll
            for (int nf2 = 0; nf2 < 4; nf2++) {
                uint32_t bh[4];
                ldsm4(bh, sB + (uint32_t)(nf2 * 16) * (LDSX * 2) + ks * 32);
                #pragma unroll
                for (int mf = 0; mf < 2; mf++) {
                    mma16816(acc[mf][2*nf2],     ah[mf], bh);
                    mma16816(acc[mf][2*nf2 + 1], ah[mf], bh + 2);
                }
            }
        }
        __syncthreads();
        if (c + 2 < NC) load_chunk(c + 2, c & 1);
    }

    // epilogue
    #pragma unroll
    for (int mf = 0; mf < 2; mf++) {
        int r0 = m0 + wm * 32 + mf * 16 + lr;
        #pragma unroll
        for (int nf = 0; nf < 8; nf++) {
            int col = n0 + wn * 64 + nf * 8 + lk2;
            float* cc = acc[mf][nf];
            float v00 = cc[0], v01 = cc[1], v10 = cc[2], v11 = cc[3];
            if (BIAS) {
                float b0 = __ldg(bias + col), b1 = __ldg(bias + col + 1);
                v00 += b0; v01 += b1; v10 += b0; v11 += b1;
            }
            if (RELU) {
                v00 = fmaxf(v00, 0.f); v01 = fmaxf(v01, 0.f);
                v10 = fmaxf(v10, 0.f); v11 = fmaxf(v11, 0.f);
            }
            if (RES) {
                float2 ra = *(const float2*)(res + (size_t)r0 * N + col);
                float2 rb = *(const float2*)(res + (size_t)(r0 + 8) * N + col);
                v00 += ra.x; v01 += ra.y; v10 += rb.x; v11 += rb.y;
            }
            if (OUTH) {
                *(__half2*)(Ch + (size_t)r0 * N + col)       = __floats2half2_rn(v00, v01);
                *(__half2*)(Ch + (size_t)(r0 + 8) * N + col) = __floats2half2_rn(v10, v11);
            } else {
                *(float2*)(Cf + (size_t)r0 * N + col)       = make_float2(v00, v01);
                *(float2*)(Cf + (size_t)(r0 + 8) * N + col) = make_float2(v10, v11);
            }
        }
    }
}

template<bool BIAS, bool RELU, bool RES, bool OUTH>
__global__ __launch_bounds__(256) void gemm_h(
    const h16* __restrict__ A, const h16* __restrict__ B,
    const float* __restrict__ bias, const float* __restrict__ res,
    float* __restrict__ Cf, h16* __restrict__ Ch, int N, int K)
{
    extern __shared__ char sm_raw[];
    gemm_body<BIAS, RELU, RES, OUTH>(
        A, B, bias, res, Cf, Ch,
        blockIdx.y * 128, blockIdx.x * 128, N, K, smem_u32(sm_raw));
}

// Fused QKV: grid.x = 24; which = bx>>3 selects weight/output.
__global__ __launch_bounds__(256) void gemm_qkv(
    const h16* __restrict__ A,
    const h16* __restrict__ B0, const h16* __restrict__ B1,
    const h16* __restrict__ B2,
    h16* __restrict__ C0, h16* __restrict__ C1, h16* __restrict__ C2)
{
    extern __shared__ char sm_raw[];
    int which = blockIdx.x >> 3;
    const h16* Bw = (which == 0) ? B0 : (which == 1) ? B1 : B2;
    h16* Cw = (which == 0) ? C0 : (which == 1) ? C1 : C2;
    gemm_body<false, false, false, true>(
        A, Bw, nullptr, nullptr, nullptr, Cw,
        blockIdx.y * 128, (blockIdx.x & 7) * 128, DD, DD, smem_u32(sm_raw));
}

// ---------------------------------------------------------------------------
// Flash attention (fp16 mma.sync): one CTA per (b, h, 128-query tile).
// 8 warps x 16 Q rows. K/V chunks of 64 keys, cp.async double-buffered.
// Online softmax in registers. Output: fp16.
// ---------------------------------------------------------------------------
#define AKST 72                       // smem row stride in h16 (144 B)

__global__ __launch_bounds__(256) void fattn_k(
    const h16* __restrict__ qg, const h16* __restrict__ kg,
    const h16* __restrict__ vg, const int* __restrict__ mask,
    h16* __restrict__ avo)
{
    __shared__ __align__(16) h16 Ks[2][64 * AKST];
    __shared__ __align__(16) h16 Vs[2][64 * AKST];
    __shared__ __align__(16) int Msk[2][64];

    int t = threadIdx.x, lane = t & 31, w = t >> 5;
    int h = blockIdx.y & (HH - 1), b = blockIdx.y >> 4;
    size_t base = (size_t)b * SS * DD + h * DKK;
    int q0 = blockIdx.x * 128 + w * 16;
    int lr = lane >> 2, q4 = lane & 3;
    int l7 = lane & 7, lg8 = (lane >> 3) & 1, lg16 = (lane >> 4) & 1;

    uint32_t qf[4][4];
    #pragma unroll
    for (int ks = 0; ks < 4; ks++) {
        int col = ks * 16 + q4 * 2;
        qf[ks][0] = *(const uint32_t*)(qg + base + (size_t)(q0 + lr) * DD + col);
        qf[ks][1] = *(const uint32_t*)(qg + base + (size_t)(q0 + lr + 8) * DD + col);
        qf[ks][2] = *(const uint32_t*)(qg + base + (size_t)(q0 + lr) * DD + col + 8);
        qf[ks][3] = *(const uint32_t*)(qg + base + (size_t)(q0 + lr + 8) * DD + col + 8);
    }

    float vacc[8][4];
    #pragma unroll
    for (int nf = 0; nf < 8; nf++)
        #pragma unroll
        for (int c = 0; c < 4; c++) vacc[nf][c] = 0.f;
    float m0 = -1e30f, m1 = -1e30f, l0 = 0.f, l1 = 0.f;

    const int NC = SS / 64;

    auto load_chunk = [&](int c, int buf) {
        int key0 = c * 64;
        uint32_t kbAddr = smem_u32(&Ks[buf][0]);
        uint32_t vbAddr = smem_u32(&Vs[buf][0]);
        #pragma unroll
        for (int i = 0; i < 2; i++) {
            int idx = t * 2 + i;
            int row = idx >> 3, seg = idx & 7;
            cp16(kbAddr + row * (AKST * 2) + seg * 16,
                 kg + base + (size_t)(key0 + row) * DD + seg * 8);
            cp16(vbAddr + row * (AKST * 2) + seg * 16,
                 vg + base + (size_t)(key0 + row) * DD + seg * 8);
        }
        if (t < 16)
            cp16(smem_u32(&Msk[buf][0]) + t * 16, mask + b * SS + key0 + t * 4);
        cp_commit();
    };

    load_chunk(0, 0);
    load_chunk(1, 1);

    for (int c = 0; c < NC; c++) {
        if (c + 1 < NC) cp_wait<1>(); else cp_wait<0>();
        __syncthreads();
        int buf = c & 1;

        float sacc[8][4];
        #pragma unroll
        for (int nf = 0; nf < 8; nf++)
            #pragma unroll
            for (int cc = 0; cc < 4; cc++) sacc[nf][cc] = 0.f;

        uint32_t ksb = smem_u32(&Ks[buf][0]);
        #pragma unroll
        for (int ks = 0; ks < 4; ks++) {
            #pragma unroll
            for (int nfp = 0; nfp < 4; nfp++) {
                uint32_t kf[4];
                uint32_t addr = ksb
                    + (uint32_t)(nfp * 16 + lg16 * 8 + l7) * (AKST * 2)
                    + ks * 32 + lg8 * 16;
                ldsm4(kf, addr);
                mma16816(sacc[2*nfp],     qf[ks], kf);
                mma16816(sacc[2*nfp + 1], qf[ks], kf + 2);
            }
        }

        #pragma unroll
        for (int nf = 0; nf < 8; nf++) {
            int col = nf * 8 + q4 * 2;
            int mk0 = Msk[buf][col], mk1 = Msk[buf][col + 1];
            float s0 = sacc[nf][0] * 0.125f, s1 = sacc[nf][1] * 0.125f;
            float s2 = sacc[nf][2] * 0.125f, s3 = sacc[nf][3] * 0.125f;
            sacc[nf][0] = mk0 ? s0 : -1e9f;
            sacc[nf][1] = mk1 ? s1 : -1e9f;
            sacc[nf][2] = mk0 ? s2 : -1e9f;
            sacc[nf][3] = mk1 ? s3 : -1e9f;
        }

        float cm0 = -1e30f, cm1 = -1e30f;
        #pragma unroll
        for (int nf = 0; nf < 8; nf++) {
            cm0 = fmaxf(cm0, fmaxf(sacc[nf][0], sacc[nf][1]));
            cm1 = fmaxf(cm1, fmaxf(sacc[nf][2], sacc[nf][3]));
        }
        cm0 = fmaxf(cm0, __shfl_xor_sync(0xffffffffu, cm0, 1));
        cm0 = fmaxf(cm0, __shfl_xor_sync(0xffffffffu, cm0, 2));
        cm1 = fmaxf(cm1, __shfl_xor_sync(0xffffffffu, cm1, 1));
        cm1 = fmaxf(cm1, __shfl_xor_sync(0xffffffffu, cm1, 2));
        float nm0 = fmaxf(m0, cm0), nm1 = fmaxf(m1, cm1);
        float sc0 = __expf(m0 - nm0), sc1 = __expf(m1 - nm1);
        l0 *= sc0; l1 *= sc1;
        #pragma unroll
        for (int nf = 0; nf < 8; nf++) {
            float p0 = __expf(sacc[nf][0] - nm0);
            float p1 = __expf(sacc[nf][1] - nm0);
            float p2 = __expf(sacc[nf][2] - nm1);
            float p3 = __expf(sacc[nf][3] - nm1);
            sacc[nf][0] = p0; sacc[nf][1] = p1;
            sacc[nf][2] = p2; sacc[nf][3] = p3;
            l0 += p0 + p1; l1 += p2 + p3;
            vacc[nf][0] *= sc0; vacc[nf][1] *= sc0;
            vacc[nf][2] *= sc1; vacc[nf][3] *= sc1;
        }
        m0 = nm0; m1 = nm1;

        uint32_t pf[4][4];
        #pragma unroll
        for (int ks = 0; ks < 4; ks++) {
            pf[ks][0] = packh(sacc[2*ks][0],     sacc[2*ks][1]);
            pf[ks][1] = packh(sacc[2*ks][2],     sacc[2*ks][3]);
            pf[ks][2] = packh(sacc[2*ks + 1][0], sacc[2*ks + 1][1]);
            pf[ks][3] = packh(sacc[2*ks + 1][2], sacc[2*ks + 1][3]);
        }

        uint32_t vsb = smem_u32(&Vs[buf][0]);
        #pragma unroll
        for (int nfp = 0; nfp < 4; nfp++) {
            #pragma unroll
            for (int ks = 0; ks < 4; ks++) {
                uint32_t vf[4];
                uint32_t addr = vsb
                    + (uint32_t)(ks * 16 + lg8 * 8 + l7) * (AKST * 2)
                    + nfp * 32 + lg16 * 16;
                ldsm4t(vf, addr);
                mma16816(vacc[2*nfp],     pf[ks], vf);
                mma16816(vacc[2*nfp + 1], pf[ks], vf + 2);
            }
        }

        __syncthreads();
        if (c + 2 < NC) load_chunk(c + 2, buf);
    }

    l0 += __shfl_xor_sync(0xffffffffu, l0, 1);
    l0 += __shfl_xor_sync(0xffffffffu, l0, 2);
    l1 += __shfl_xor_sync(0xffffffffu, l1, 1);
    l1 += __shfl_xor_sync(0xffffffffu, l1, 2);
    float r0 = 1.0f / l0, r1 = 1.0f / l1;

    #pragma unroll
    for (int nf = 0; nf < 8; nf++) {
        int col = nf * 8 + q4 * 2;
        size_t o0 = base + (size_t)(q0 + lr) * DD + col;
        size_t o1 = base + (size_t)(q0 + lr + 8) * DD + col;
        *(__half2*)(avo + o0) = __floats2half2_rn(vacc[nf][0] * r0, vacc[nf][1] * r0);
        *(__half2*)(avo + o1) = __floats2half2_rn(vacc[nf][2] * r1, vacc[nf][3] * r1);
    }
}

// ---------------------------------------------------------------------------
// Driver
// ---------------------------------------------------------------------------
extern "C" void kernel_launch(void* const* d_in, const int* in_sizes, int n_in,
                              void* d_out, int out_size)
{
    const float* x      = (const float*)d_in[0];
    const int*   mask   = (const int*)  d_in[1];
    const float* wq     = (const float*)d_in[2];
    const float* wk     = (const float*)d_in[3];
    const float* wv     = (const float*)d_in[4];
    const float* wo     = (const float*)d_in[5];
    const float* w1     = (const float*)d_in[6];
    const float* b1     = (const float*)d_in[7];
    const float* w2     = (const float*)d_in[8];
    const float* b2     = (const float*)d_in[9];
    const float* alpha1 = (const float*)d_in[10];
    const float* bias1  = (const float*)d_in[11];
    const float* alpha2 = (const float*)d_in[12];
    const float* bias2  = (const float*)d_in[13];
    float* out = (float*)d_out;

    h16 *xn, *qb, *kb, *vb, *av, *xn2, *hb;
    h16 *wqh, *wkh, *wvh, *woh, *w1h, *w2h;
    float *x1;
    cudaGetSymbolAddress((void**)&xn,   g_xn);
    cudaGetSymbolAddress((void**)&qb,   g_qb);   cudaGetSymbolAddress((void**)&kb,   g_kb);
    cudaGetSymbolAddress((void**)&vb,   g_vb);
    cudaGetSymbolAddress((void**)&av,   g_av);
    cudaGetSymbolAddress((void**)&x1,   g_x1);
    cudaGetSymbolAddress((void**)&xn2,  g_xn2);
    cudaGetSymbolAddress((void**)&hb,   g_hb);
    cudaGetSymbolAddress((void**)&wqh,  g_wqh);
    cudaGetSymbolAddress((void**)&wkh,  g_wkh);
    cudaGetSymbolAddress((void**)&wvh,  g_wvh);
    cudaGetSymbolAddress((void**)&woh,  g_woh);
    cudaGetSymbolAddress((void**)&w1h,  g_w1h);
    cudaGetSymbolAddress((void**)&w2h,  g_w2h);

    // 0. weights -> fp16
    cvt_k<<<(DD*DD/4 + 255)/256, 256>>>(wq, wqh, DD*DD/4);
    cvt_k<<<(DD*DD/4 + 255)/256, 256>>>(wk, wkh, DD*DD/4);
    cvt_k<<<(DD*DD/4 + 255)/256, 256>>>(wv, wvh, DD*DD/4);
    cvt_k<<<(DD*DD/4 + 255)/256, 256>>>(wo, woh, DD*DD/4);
    cvt_k<<<(DFFN*DD/4 + 255)/256, 256>>>(w1, w1h, DFFN*DD/4);
    cvt_k<<<(DD*DFFN/4 + 255)/256, 256>>>(w2, w2h, DD*DFFN/4);

    // 1. LN1 -> fp16
    layernorm_k<<<NTOK, 256>>>(x, alpha1, bias1, xn);

    // 2. fused Q/K/V projections (fp16)
    dim3 gQKV(3 * (DD / 128), NTOK / 128);  // (24, 32)
    gemm_qkv<<<gQKV, 256, GEMM_SMEM>>>(xn, wqh, wkh, wvh, qb, kb, vb);

    // 3. flash attention -> fp16
    dim3 gAttn(SS / 128, BB * HH);          // (16, 32)
    fattn_k<<<gAttn, 256>>>(qb, kb, vb, mask, av);

    // 4. output projection + residual(x) -> x1 fp32
    dim3 gProj(DD / 128, NTOK / 128);       // (8, 32)
    gemm_h<false,false,true,false><<<gProj, 256, GEMM_SMEM>>>(
        av, woh, nullptr, x, x1, nullptr, DD, DD);

    // 5. LN2 -> fp16
    layernorm_k<<<NTOK, 256>>>(x1, alpha2, bias2, xn2);

    // 6. FFN up: relu(xn2@w1^T + b1) -> fp16
    dim3 gF1(DFFN / 128, NTOK / 128);       // (32, 32)
    gemm_h<true,true,false,true><<<gF1, 256, GEMM_SMEM>>>(
        xn2, w1h, b1, nullptr, nullptr, hb, DFFN, DD);

    // 7. FFN down: h@w2^T + b2 + x1 -> out fp32
    gemm_h<true,false,true,false><<<gProj, 256, GEMM_SMEM>>>(
        hb, w2h, b2, x1, out, nullptr, DD, DFFN);
}

// round 8
// speedup vs baseline: 7.9032x; 1.0491x over previous
#include <cuda_runtime.h>
#include <cuda_fp16.h>
#include <math.h>
#include <stdint.h>

// Problem constants
#define BB 2
#define SS 2048
#define DD 1024
#define HH 16
#define DKK 64
#define DFFN 4096
#define NTOK (BB*SS)          // 4096
#define LN_EPS 1e-6f

typedef __half h16;

// ---------------------------------------------------------------------------
// Scratch (static __device__ arrays: allocation-guard-safe)
// ---------------------------------------------------------------------------
__device__ h16   g_xn  [(size_t)NTOK*DD];
__device__ h16   g_qb  [(size_t)NTOK*DD];
__device__ h16   g_kb  [(size_t)NTOK*DD];
__device__ h16   g_vb  [(size_t)NTOK*DD];
__device__ h16   g_av  [(size_t)NTOK*DD];
__device__ float g_x1  [(size_t)NTOK*DD];
__device__ h16   g_xn2 [(size_t)NTOK*DD];
__device__ h16   g_hb  [(size_t)NTOK*DFFN];
__device__ h16   g_wqh [(size_t)DD*DD];
__device__ h16   g_wkh [(size_t)DD*DD];
__device__ h16   g_wvh [(size_t)DD*DD];
__device__ h16   g_woh [(size_t)DD*DD];
__device__ h16   g_w1h [(size_t)DFFN*DD];
__device__ h16   g_w2h [(size_t)DD*DFFN];

// ---------------------------------------------------------------------------
// PTX helpers (cp.async + mma.sync + ldmatrix)
// ---------------------------------------------------------------------------
__device__ __forceinline__ uint32_t smem_u32(const void* p) {
    uint32_t a;
    asm("{ .reg .u64 t; cvta.to.shared.u64 t, %1; cvt.u32.u64 %0, t; }"
        : "=r"(a) : "l"(p));
    return a;
}
__device__ __forceinline__ void cp16(uint32_t d, const void* s) {
    asm volatile("cp.async.cg.shared.global [%0], [%1], 16;\n" :: "r"(d), "l"(s));
}
__device__ __forceinline__ void cp_commit() { asm volatile("cp.async.commit_group;\n" ::); }
template<int N> __device__ __forceinline__ void cp_wait() {
    asm volatile("cp.async.wait_group %0;\n" :: "n"(N));
}

__device__ __forceinline__ void mma16816(float* c, const uint32_t* a, const uint32_t* b) {
    asm volatile(
        "mma.sync.aligned.m16n8k16.row.col.f32.f16.f16.f32 "
        "{%0,%1,%2,%3}, {%4,%5,%6,%7}, {%8,%9}, {%0,%1,%2,%3};"
        : "+f"(c[0]), "+f"(c[1]), "+f"(c[2]), "+f"(c[3])
        : "r"(a[0]), "r"(a[1]), "r"(a[2]), "r"(a[3]), "r"(b[0]), "r"(b[1]));
}
__device__ __forceinline__ void ldsm4(uint32_t* r, uint32_t addr) {
    asm volatile("ldmatrix.sync.aligned.m8n8.x4.shared.b16 {%0,%1,%2,%3}, [%4];"
        : "=r"(r[0]), "=r"(r[1]), "=r"(r[2]), "=r"(r[3]) : "r"(addr));
}
__device__ __forceinline__ void ldsm4t(uint32_t* r, uint32_t addr) {
    asm volatile("ldmatrix.sync.aligned.m8n8.x4.trans.shared.b16 {%0,%1,%2,%3}, [%4];"
        : "=r"(r[0]), "=r"(r[1]), "=r"(r[2]), "=r"(r[3]) : "r"(addr));
}
__device__ __forceinline__ uint32_t packh(float lo, float hi) {
    __half2 t = __floats2half2_rn(lo, hi);
    return *(uint32_t*)&t;
}

// ---------------------------------------------------------------------------
// Reductions
// ---------------------------------------------------------------------------
__device__ __forceinline__ float warpReduceSum(float v) {
    #pragma unroll
    for (int o = 16; o > 0; o >>= 1) v += __shfl_xor_sync(0xffffffffu, v, o);
    return v;
}

// ---------------------------------------------------------------------------
// Fused convert of all 6 weight matrices fp32 -> fp16, one launch.
// Flat index over concatenated [wq|wk|wv|wo|w1|w2] in float4 units.
// ---------------------------------------------------------------------------
#define CVT_Q (DD*DD/4)        // 262144 (= 2^18)
#define CVT_F (DFFN*DD/4)      // 1048576
#define CVT_TOTAL (4*CVT_Q + 2*CVT_F)   // 3145728

__global__ __launch_bounds__(256) void cvt_all(
    const float* __restrict__ wq, const float* __restrict__ wk,
    const float* __restrict__ wv, const float* __restrict__ wo,
    const float* __restrict__ w1, const float* __restrict__ w2,
    h16* __restrict__ oq, h16* __restrict__ ok, h16* __restrict__ ov,
    h16* __restrict__ oo, h16* __restrict__ o1, h16* __restrict__ o2)
{
    int i = blockIdx.x * 256 + threadIdx.x;
    if (i >= CVT_TOTAL) return;
    const float* src; h16* dst; int off;
    if (i < 4*CVT_Q) {
        int w = i >> 18; off = i & (CVT_Q - 1);
        src = (w==0) ? wq : (w==1) ? wk : (w==2) ? wv : wo;
        dst = (w==0) ? oq : (w==1) ? ok : (w==2) ? ov : oo;
    } else if (i < 4*CVT_Q + CVT_F) {
        src = w1; dst = o1; off = i - 4*CVT_Q;
    } else {
        src = w2; dst = o2; off = i - 4*CVT_Q - CVT_F;
    }
    float4 v = ((const float4*)src)[off];
    ((__half2*)dst)[off*2]   = __floats2half2_rn(v.x, v.y);
    ((__half2*)dst)[off*2+1] = __floats2half2_rn(v.z, v.w);
}

// ---------------------------------------------------------------------------
// LayerNorm -> fp16. One 256-thread block per row of 1024.
// torch semantics: alpha * (x - mean) / (sqrt(var_unbiased) + eps) + bias
// ---------------------------------------------------------------------------
__global__ __launch_bounds__(256) void layernorm_k(
    const float* __restrict__ x, const float* __restrict__ alpha,
    const float* __restrict__ beta, h16* __restrict__ oh)
{
    int row = blockIdx.x;
    const float* xr = x + (size_t)row * DD;
    int i = threadIdx.x * 4;
    float4 xv = *(const float4*)(xr + i);
    float s  = xv.x + xv.y + xv.z + xv.w;
    float s2 = xv.x*xv.x + xv.y*xv.y + xv.z*xv.z + xv.w*xv.w;

    __shared__ float rs[8], rs2[8];
    __shared__ float smean, sinv;
    s  = warpReduceSum(s);
    s2 = warpReduceSum(s2);
    int w = threadIdx.x >> 5, l = threadIdx.x & 31;
    if (l == 0) { rs[w] = s; rs2[w] = s2; }
    __syncthreads();
    if (threadIdx.x == 0) {
        float S = 0.f, S2 = 0.f;
        #pragma unroll
        for (int k = 0; k < 8; k++) { S += rs[k]; S2 += rs2[k]; }
        float mean = S * (1.0f / (float)DD);
        float var  = (S2 - (float)DD * mean * mean) * (1.0f / (float)(DD - 1));
        var = fmaxf(var, 0.0f);
        smean = mean;
        sinv  = 1.0f / (sqrtf(var) + LN_EPS);
    }
    __syncthreads();
    float m = smean, inv = sinv;
    float4 av = *(const float4*)(alpha + i);
    float4 bv = *(const float4*)(beta  + i);
    float o0 = av.x * (xv.x - m) * inv + bv.x;
    float o1 = av.y * (xv.y - m) * inv + bv.y;
    float o2 = av.z * (xv.z - m) * inv + bv.z;
    float o3 = av.w * (xv.w - m) * inv + bv.w;
    size_t off = (size_t)row * DD + i;
    ((__half2*)(oh + off))[0] = __floats2half2_rn(o0, o1);
    ((__half2*)(oh + off))[1] = __floats2half2_rn(o2, o3);
}

// ---------------------------------------------------------------------------
// GEMM tiling: 128x128 tile, BK=32, 256 threads (8 warps 4x2; 32x64/warp),
// single fp16 product, 3-stage cp.async pipeline, ONE sync per chunk.
// ---------------------------------------------------------------------------
#define BK 32
#define LDSX 40                       // padded row stride in h16 elems (80B)
#define MATB (128 * LDSX * 2)         // 10240 B per matrix tile
#define STAGE (2 * MATB)              // A, B
#define NSTG 3
#define GEMM_SMEM (NSTG * STAGE)      // 61440 B

__device__ __forceinline__ uint32_t a_ldsm_off(int lane) {
    int r = ((lane >> 3) & 1) * 8 + (lane & 7);
    int c = (lane >> 4) * 8;
    return (uint32_t)(r * LDSX + c) * 2;
}
__device__ __forceinline__ uint32_t b_ldsm_off(int lane) {
    int r = (lane >> 4) * 8 + (lane & 7);
    int c = ((lane >> 3) & 1) * 8;
    return (uint32_t)(r * LDSX + c) * 2;
}

template<bool BIAS, bool RELU, bool RES, bool OUTH>
__device__ __forceinline__ void gemm_body(
    const h16* __restrict__ A, const h16* __restrict__ B,
    const float* __restrict__ bias, const float* __restrict__ res,
    float* __restrict__ Cf, h16* __restrict__ Ch,
    int m0, int n0, int N, int K, uint32_t sbase)
{
    int tid = threadIdx.x, lane = tid & 31, wid = tid >> 5;
    int wm = wid & 3, wn = wid >> 2;
    int lr = lane >> 2, lk2 = (lane & 3) * 2;
    uint32_t aoff = a_ldsm_off(lane) + (uint32_t)(wm * 32) * (LDSX * 2);
    uint32_t boff = b_ldsm_off(lane) + (uint32_t)(wn * 64) * (LDSX * 2);

    float acc[2][8][4];
    #pragma unroll
    for (int a = 0; a < 2; a++)
        #pragma unroll
        for (int b = 0; b < 8; b++)
            #pragma unroll
            for (int c = 0; c < 4; c++) acc[a][b][c] = 0.f;

    const int NC = K / BK;

    auto load_chunk = [&](int c, int buf) {
        int kc = c * BK;
        uint32_t base = sbase + buf * STAGE;
        #pragma unroll
        for (int T = 0; T < 2; T++) {
            const h16* src = (T == 0) ? A : B;
            int r0 = (T == 0) ? m0 : n0;
            uint32_t mb = base + T * MATB;
            int row = tid >> 1, c16 = tid & 1;
            cp16(mb + row * (LDSX * 2) + c16 * 32,
                 src + (size_t)(r0 + row) * K + kc + c16 * 16);
            cp16(mb + row * (LDSX * 2) + c16 * 32 + 16,
                 src + (size_t)(r0 + row) * K + kc + c16 * 16 + 8);
        }
        cp_commit();
    };

    load_chunk(0, 0);
    load_chunk(1, 1);

    for (int c = 0; c < NC; c++) {
        if (c + 2 < NC) cp_wait<1>(); else cp_wait<0>();
        __syncthreads();
        // Prefetch chunk c+2 into slot (c+2)%3 == (c-1)%3; all warps passed the
        // sync above, so every reader of that slot (iter c-1) is done.
        if (c + 2 < NC) load_chunk(c + 2, (c + 2) % NSTG);

        uint32_t stg = sbase + (c % NSTG) * STAGE;
        uint32_t sA = stg + aoff;
        uint32_t sB = stg + MATB + boff;

        #pragma unroll
        for (int ks = 0; ks < 2; ks++) {
            uint32_t ah[2][4];
            #pragma unroll
            for (int mf = 0; mf < 2; mf++)
                ldsm4(ah[mf], sA + (uint32_t)(mf * 16) * (LDSX * 2) + ks * 32);
            #pragma unroll
            for (int nf2 = 0; nf2 < 4; nf2++) {
                uint32_t bh[4];
                ldsm4(bh, sB + (uint32_t)(nf2 * 16) * (LDSX * 2) + ks * 32);
                #pragma unroll
                for (int mf = 0; mf < 2; mf++) {
                    mma16816(acc[mf][2*nf2],     ah[mf], bh);
                    mma16816(acc[mf][2*nf2 + 1], ah[mf], bh + 2);
                }
            }
        }
    }

    // epilogue
    #pragma unroll
    for (int mf = 0; mf < 2; mf++) {
        int r0 = m0 + wm * 32 + mf * 16 + lr;
        #pragma unroll
        for (int nf = 0; nf < 8; nf++) {
            int col = n0 + wn * 64 + nf * 8 + lk2;
            float* cc = acc[mf][nf];
            float v00 = cc[0], v01 = cc[1], v10 = cc[2], v11 = cc[3];
            if (BIAS) {
                float b0 = __ldg(bias + col), b1 = __ldg(bias + col + 1);
                v00 += b0; v01 += b1; v10 += b0; v11 += b1;
            }
            if (RELU) {
                v00 = fmaxf(v00, 0.f); v01 = fmaxf(v01, 0.f);
                v10 = fmaxf(v10, 0.f); v11 = fmaxf(v11, 0.f);
            }
            if (RES) {
                float2 ra = *(const float2*)(res + (size_t)r0 * N + col);
                float2 rb = *(const float2*)(res + (size_t)(r0 + 8) * N + col);
                v00 += ra.x; v01 += ra.y; v10 += rb.x; v11 += rb.y;
            }
            if (OUTH) {
                *(__half2*)(Ch + (size_t)r0 * N + col)       = __floats2half2_rn(v00, v01);
                *(__half2*)(Ch + (size_t)(r0 + 8) * N + col) = __floats2half2_rn(v10, v11);
            } else {
                *(float2*)(Cf + (size_t)r0 * N + col)       = make_float2(v00, v01);
                *(float2*)(Cf + (size_t)(r0 + 8) * N + col) = make_float2(v10, v11);
            }
        }
    }
}

template<bool BIAS, bool RELU, bool RES, bool OUTH>
__global__ __launch_bounds__(256) void gemm_h(
    const h16* __restrict__ A, const h16* __restrict__ B,
    const float* __restrict__ bias, const float* __restrict__ res,
    float* __restrict__ Cf, h16* __restrict__ Ch, int N, int K)
{
    extern __shared__ char sm_raw[];
    gemm_body<BIAS, RELU, RES, OUTH>(
        A, B, bias, res, Cf, Ch,
        blockIdx.y * 128, blockIdx.x * 128, N, K, smem_u32(sm_raw));
}

// Fused QKV: grid.x = 24; which = bx>>3 selects weight/output.
__global__ __launch_bounds__(256) void gemm_qkv(
    const h16* __restrict__ A,
    const h16* __restrict__ B0, const h16* __restrict__ B1,
    const h16* __restrict__ B2,
    h16* __restrict__ C0, h16* __restrict__ C1, h16* __restrict__ C2)
{
    extern __shared__ char sm_raw[];
    int which = blockIdx.x >> 3;
    const h16* Bw = (which == 0) ? B0 : (which == 1) ? B1 : B2;
    h16* Cw = (which == 0) ? C0 : (which == 1) ? C1 : C2;
    gemm_body<false, false, false, true>(
        A, Bw, nullptr, nullptr, nullptr, Cw,
        blockIdx.y * 128, (blockIdx.x & 7) * 128, DD, DD, smem_u32(sm_raw));
}

// ---------------------------------------------------------------------------
// Flash attention (fp16 mma.sync): one CTA per (b, h, 128-query tile).
// 8 warps x 16 Q rows. K/V chunks of 64 keys, 3-stage cp.async pipeline,
// ONE sync per chunk. Online softmax in registers. Output: fp16.
// Dynamic smem layout: Ks[3][64*AKST] | Vs[3][64*AKST] | Msk[3][64]
// ---------------------------------------------------------------------------
#define AKST 72                       // smem row stride in h16 (144 B)
#define AKBUF (64 * AKST * 2)         // 9216 B per K (or V) stage
#define AVS_OFF (NSTG * AKBUF)        // 27648
#define AMSK_OFF (2 * NSTG * AKBUF)   // 55296
#define ATTN_SMEM (AMSK_OFF + NSTG * 64 * 4)   // 56064 B

__global__ __launch_bounds__(256) void fattn_k(
    const h16* __restrict__ qg, const h16* __restrict__ kg,
    const h16* __restrict__ vg, const int* __restrict__ mask,
    h16* __restrict__ avo)
{
    extern __shared__ char sm_raw[];
    uint32_t sbase = smem_u32(sm_raw);
    int* msk_s = (int*)(sm_raw + AMSK_OFF);

    int t = threadIdx.x, lane = t & 31, w = t >> 5;
    int h = blockIdx.y & (HH - 1), b = blockIdx.y >> 4;
    size_t base = (size_t)b * SS * DD + h * DKK;
    int q0 = blockIdx.x * 128 + w * 16;
    int lr = lane >> 2, q4 = lane & 3;
    int l7 = lane & 7, lg8 = (lane >> 3) & 1, lg16 = (lane >> 4) & 1;

    uint32_t qf[4][4];
    #pragma unroll
    for (int ks = 0; ks < 4; ks++) {
        int col = ks * 16 + q4 * 2;
        qf[ks][0] = *(const uint32_t*)(qg + base + (size_t)(q0 + lr) * DD + col);
        qf[ks][1] = *(const uint32_t*)(qg + base + (size_t)(q0 + lr + 8) * DD + col);
        qf[ks][2] = *(const uint32_t*)(qg + base + (size_t)(q0 + lr) * DD + col + 8);
        qf[ks][3] = *(const uint32_t*)(qg + base + (size_t)(q0 + lr + 8) * DD + col + 8);
    }

    float vacc[8][4];
    #pragma unroll
    for (int nf = 0; nf < 8; nf++)
        #pragma unroll
        for (int c = 0; c < 4; c++) vacc[nf][c] = 0.f;
    float m0 = -1e30f, m1 = -1e30f, l0 = 0.f, l1 = 0.f;

    const int NC = SS / 64;

    auto load_chunk = [&](int c, int buf) {
        int key0 = c * 64;
        uint32_t kbAddr = sbase + buf * AKBUF;
        uint32_t vbAddr = sbase + AVS_OFF + buf * AKBUF;
        #pragma unroll
        for (int i = 0; i < 2; i++) {
            int idx = t * 2 + i;
            int row = idx >> 3, seg = idx & 7;
            cp16(kbAddr + row * (AKST * 2) + seg * 16,
                 kg + base + (size_t)(key0 + row) * DD + seg * 8);
            cp16(vbAddr + row * (AKST * 2) + seg * 16,
                 vg + base + (size_t)(key0 + row) * DD + seg * 8);
        }
        if (t < 16)
            cp16(sbase + AMSK_OFF + buf * 256 + t * 16,
                 mask + b * SS + key0 + t * 4);
        cp_commit();
    };

    load_chunk(0, 0);
    load_chunk(1, 1);

    for (int c = 0; c < NC; c++) {
        if (c + 2 < NC) cp_wait<1>(); else cp_wait<0>();
        __syncthreads();
        if (c + 2 < NC) load_chunk(c + 2, (c + 2) % NSTG);
        int buf = c % NSTG;

        float sacc[8][4];
        #pragma unroll
        for (int nf = 0; nf < 8; nf++)
            #pragma unroll
            for (int cc = 0; cc < 4; cc++) sacc[nf][cc] = 0.f;

        uint32_t ksb = sbase + buf * AKBUF;
        #pragma unroll
        for (int ks = 0; ks < 4; ks++) {
            #pragma unroll
            for (int nfp = 0; nfp < 4; nfp++) {
                uint32_t kf[4];
                uint32_t addr = ksb
                    + (uint32_t)(nfp * 16 + lg16 * 8 + l7) * (AKST * 2)
                    + ks * 32 + lg8 * 16;
                ldsm4(kf, addr);
                mma16816(sacc[2*nfp],     qf[ks], kf);
                mma16816(sacc[2*nfp + 1], qf[ks], kf + 2);
            }
        }

        #pragma unroll
        for (int nf = 0; nf < 8; nf++) {
            int col = nf * 8 + q4 * 2;
            int mk0 = msk_s[buf * 64 + col], mk1 = msk_s[buf * 64 + col + 1];
            float s0 = sacc[nf][0] * 0.125f, s1 = sacc[nf][1] * 0.125f;
            float s2 = sacc[nf][2] * 0.125f, s3 = sacc[nf][3] * 0.125f;
            sacc[nf][0] = mk0 ? s0 : -1e9f;
            sacc[nf][1] = mk1 ? s1 : -1e9f;
            sacc[nf][2] = mk0 ? s2 : -1e9f;
            sacc[nf][3] = mk1 ? s3 : -1e9f;
        }

        float cm0 = -1e30f, cm1 = -1e30f;
        #pragma unroll
        for (int nf = 0; nf < 8; nf++) {
            cm0 = fmaxf(cm0, fmaxf(sacc[nf][0], sacc[nf][1]));
            cm1 = fmaxf(cm1, fmaxf(sacc[nf][2], sacc[nf][3]));
        }
        cm0 = fmaxf(cm0, __shfl_xor_sync(0xffffffffu, cm0, 1));
        cm0 = fmaxf(cm0, __shfl_xor_sync(0xffffffffu, cm0, 2));
        cm1 = fmaxf(cm1, __shfl_xor_sync(0xffffffffu, cm1, 1));
        cm1 = fmaxf(cm1, __shfl_xor_sync(0xffffffffu, cm1, 2));
        float nm0 = fmaxf(m0, cm0), nm1 = fmaxf(m1, cm1);
        float sc0 = __expf(m0 - nm0), sc1 = __expf(m1 - nm1);
        l0 *= sc0; l1 *= sc1;
        #pragma unroll
        for (int nf = 0; nf < 8; nf++) {
            float p0 = __expf(sacc[nf][0] - nm0);
            float p1 = __expf(sacc[nf][1] - nm0);
            float p2 = __expf(sacc[nf][2] - nm1);
            float p3 = __expf(sacc[nf][3] - nm1);
            sacc[nf][0] = p0; sacc[nf][1] = p1;
            sacc[nf][2] = p2; sacc[nf][3] = p3;
            l0 += p0 + p1; l1 += p2 + p3;
            vacc[nf][0] *= sc0; vacc[nf][1] *= sc0;
            vacc[nf][2] *= sc1; vacc[nf][3] *= sc1;
        }
        m0 = nm0; m1 = nm1;

        uint32_t pf[4][4];
        #pragma unroll
        for (int ks = 0; ks < 4; ks++) {
            pf[ks][0] = packh(sacc[2*ks][0],     sacc[2*ks][1]);
            pf[ks][1] = packh(sacc[2*ks][2],     sacc[2*ks][3]);
            pf[ks][2] = packh(sacc[2*ks + 1][0], sacc[2*ks + 1][1]);
            pf[ks][3] = packh(sacc[2*ks + 1][2], sacc[2*ks + 1][3]);
        }

        uint32_t vsb = sbase + AVS_OFF + buf * AKBUF;
        #pragma unroll
        for (int nfp = 0; nfp < 4; nfp++) {
            #pragma unroll
            for (int ks = 0; ks < 4; ks++) {
                uint32_t vf[4];
                uint32_t addr = vsb
                    + (uint32_t)(ks * 16 + lg8 * 8 + l7) * (AKST * 2)
                    + nfp * 32 + lg16 * 16;
                ldsm4t(vf, addr);
                mma16816(vacc[2*nfp],     pf[ks], vf);
                mma16816(vacc[2*nfp + 1], pf[ks], vf + 2);
            }
        }
    }

    l0 += __shfl_xor_sync(0xffffffffu, l0, 1);
    l0 += __shfl_xor_sync(0xffffffffu, l0, 2);
    l1 += __shfl_xor_sync(0xffffffffu, l1, 1);
    l1 += __shfl_xor_sync(0xffffffffu, l1, 2);
    float r0 = 1.0f / l0, r1 = 1.0f / l1;

    #pragma unroll
    for (int nf = 0; nf < 8; nf++) {
        int col = nf * 8 + q4 * 2;
        size_t o0 = base + (size_t)(q0 + lr) * DD + col;
        size_t o1 = base + (size_t)(q0 + lr + 8) * DD + col;
        *(__half2*)(avo + o0) = __floats2half2_rn(vacc[nf][0] * r0, vacc[nf][1] * r0);
        *(__half2*)(avo + o1) = __floats2half2_rn(vacc[nf][2] * r1, vacc[nf][3] * r1);
    }
}

// ---------------------------------------------------------------------------
// Driver
// ---------------------------------------------------------------------------
extern "C" void kernel_launch(void* const* d_in, const int* in_sizes, int n_in,
                              void* d_out, int out_size)
{
    const float* x      = (const float*)d_in[0];
    const int*   mask   = (const int*)  d_in[1];
    const float* wq     = (const float*)d_in[2];
    const float* wk     = (const float*)d_in[3];
    const float* wv     = (const float*)d_in[4];
    const float* wo     = (const float*)d_in[5];
    const float* w1     = (const float*)d_in[6];
    const float* b1     = (const float*)d_in[7];
    const float* w2     = (const float*)d_in[8];
    const float* b2     = (const float*)d_in[9];
    const float* alpha1 = (const float*)d_in[10];
    const float* bias1  = (const float*)d_in[11];
    const float* alpha2 = (const float*)d_in[12];
    const float* bias2  = (const float*)d_in[13];
    float* out = (float*)d_out;

    h16 *xn, *qb, *kb, *vb, *av, *xn2, *hb;
    h16 *wqh, *wkh, *wvh, *woh, *w1h, *w2h;
    float *x1;
    cudaGetSymbolAddress((void**)&xn,   g_xn);
    cudaGetSymbolAddress((void**)&qb,   g_qb);   cudaGetSymbolAddress((void**)&kb,   g_kb);
    cudaGetSymbolAddress((void**)&vb,   g_vb);
    cudaGetSymbolAddress((void**)&av,   g_av);
    cudaGetSymbolAddress((void**)&x1,   g_x1);
    cudaGetSymbolAddress((void**)&xn2,  g_xn2);
    cudaGetSymbolAddress((void**)&hb,   g_hb);
    cudaGetSymbolAddress((void**)&wqh,  g_wqh);
    cudaGetSymbolAddress((void**)&wkh,  g_wkh);
    cudaGetSymbolAddress((void**)&wvh,  g_wvh);
    cudaGetSymbolAddress((void**)&woh,  g_woh);
    cudaGetSymbolAddress((void**)&w1h,  g_w1h);
    cudaGetSymbolAddress((void**)&w2h,  g_w2h);

    cudaFuncSetAttribute(gemm_h<false,false,true,false>,
                         cudaFuncAttributeMaxDynamicSharedMemorySize, GEMM_SMEM);
    cudaFuncSetAttribute(gemm_h<true,true,false,true>,
                         cudaFuncAttributeMaxDynamicSharedMemorySize, GEMM_SMEM);
    cudaFuncSetAttribute(gemm_h<true,false,true,false>,
                         cudaFuncAttributeMaxDynamicSharedMemorySize, GEMM_SMEM);
    cudaFuncSetAttribute(gemm_qkv,
                         cudaFuncAttributeMaxDynamicSharedMemorySize, GEMM_SMEM);
    cudaFuncSetAttribute(fattn_k,
                         cudaFuncAttributeMaxDynamicSharedMemorySize, ATTN_SMEM);

    // 0. all weights -> fp16, single launch
    cvt_all<<<(CVT_TOTAL + 255)/256, 256>>>(
        wq, wk, wv, wo, w1, w2, wqh, wkh, wvh, woh, w1h, w2h);

    // 1. LN1 -> fp16
    layernorm_k<<<NTOK, 256>>>(x, alpha1, bias1, xn);

    // 2. fused Q/K/V projections (fp16)
    dim3 gQKV(3 * (DD / 128), NTOK / 128);  // (24, 32)
    gemm_qkv<<<gQKV, 256, GEMM_SMEM>>>(xn, wqh, wkh, wvh, qb, kb, vb);

    // 3. flash attention -> fp16
    dim3 gAttn(SS / 128, BB * HH);          // (16, 32)
    fattn_k<<<gAttn, 256, ATTN_SMEM>>>(qb, kb, vb, mask, av);

    // 4. output projection + residual(x) -> x1 fp32
    dim3 gProj(DD / 128, NTOK / 128);       // (8, 32)
    gemm_h<false,false,true,false><<<gProj, 256, GEMM_SMEM>>>(
        av, woh, nullptr, x, x1, nullptr, DD, DD);

    // 5. LN2 -> fp16
    layernorm_k<<<NTOK, 256>>>(x1, alpha2, bias2, xn2);

    // 6. FFN up: relu(xn2@w1^T + b1) -> fp16
    dim3 gF1(DFFN / 128, NTOK / 128);       // (32, 32)
    gemm_h<true,true,false,true><<<gF1, 256, GEMM_SMEM>>>(
        xn2, w1h, b1, nullptr, nullptr, hb, DFFN, DD);

    // 7. FFN down: h@w2^T + b2 + x1 -> out fp32
    gemm_h<true,false,true,false><<<gProj, 256, GEMM_SMEM>>>(
        hb, w2h, b2, x1, out, nullptr, DD, DFFN);
}

// round 9
// speedup vs baseline: 8.2317x; 1.0416x over previous
#include <cuda_runtime.h>
#include <cuda_fp16.h>
#include <math.h>
#include <stdint.h>

// Problem constants
#define BB 2
#define SS 2048
#define DD 1024
#define HH 16
#define DKK 64
#define DFFN 4096
#define NTOK (BB*SS)          // 4096
#define LN_EPS 1e-6f

typedef __half h16;

// ---------------------------------------------------------------------------
// Scratch (static __device__ arrays: allocation-guard-safe)
// ---------------------------------------------------------------------------
__device__ h16   g_xn  [(size_t)NTOK*DD];
__device__ h16   g_qb  [(size_t)NTOK*DD];
__device__ h16   g_kb  [(size_t)NTOK*DD];
__device__ h16   g_vb  [(size_t)NTOK*DD];
__device__ h16   g_av  [(size_t)NTOK*DD];
__device__ float g_x1  [(size_t)NTOK*DD];
__device__ h16   g_xn2 [(size_t)NTOK*DD];
__device__ h16   g_hb  [(size_t)NTOK*DFFN];
__device__ h16   g_wqh [(size_t)DD*DD];
__device__ h16   g_wkh [(size_t)DD*DD];
__device__ h16   g_wvh [(size_t)DD*DD];
__device__ h16   g_woh [(size_t)DD*DD];
__device__ h16   g_w1h [(size_t)DFFN*DD];
__device__ h16   g_w2h [(size_t)DD*DFFN];

// ---------------------------------------------------------------------------
// PTX helpers (cp.async + mma.sync + ldmatrix + ex2)
// ---------------------------------------------------------------------------
__device__ __forceinline__ uint32_t smem_u32(const void* p) {
    uint32_t a;
    asm("{ .reg .u64 t; cvta.to.shared.u64 t, %1; cvt.u32.u64 %0, t; }"
        : "=r"(a) : "l"(p));
    return a;
}
__device__ __forceinline__ void cp16(uint32_t d, const void* s) {
    asm volatile("cp.async.cg.shared.global [%0], [%1], 16;\n" :: "r"(d), "l"(s));
}
__device__ __forceinline__ void cp_commit() { asm volatile("cp.async.commit_group;\n" ::); }
template<int N> __device__ __forceinline__ void cp_wait() {
    asm volatile("cp.async.wait_group %0;\n" :: "n"(N));
}

__device__ __forceinline__ void mma16816(float* c, const uint32_t* a, const uint32_t* b) {
    asm volatile(
        "mma.sync.aligned.m16n8k16.row.col.f32.f16.f16.f32 "
        "{%0,%1,%2,%3}, {%4,%5,%6,%7}, {%8,%9}, {%0,%1,%2,%3};"
        : "+f"(c[0]), "+f"(c[1]), "+f"(c[2]), "+f"(c[3])
        : "r"(a[0]), "r"(a[1]), "r"(a[2]), "r"(a[3]), "r"(b[0]), "r"(b[1]));
}
__device__ __forceinline__ void ldsm4(uint32_t* r, uint32_t addr) {
    asm volatile("ldmatrix.sync.aligned.m8n8.x4.shared.b16 {%0,%1,%2,%3}, [%4];"
        : "=r"(r[0]), "=r"(r[1]), "=r"(r[2]), "=r"(r[3]) : "r"(addr));
}
__device__ __forceinline__ void ldsm4t(uint32_t* r, uint32_t addr) {
    asm volatile("ldmatrix.sync.aligned.m8n8.x4.trans.shared.b16 {%0,%1,%2,%3}, [%4];"
        : "=r"(r[0]), "=r"(r[1]), "=r"(r[2]), "=r"(r[3]) : "r"(addr));
}
__device__ __forceinline__ uint32_t packh(float lo, float hi) {
    __half2 t = __floats2half2_rn(lo, hi);
    return *(uint32_t*)&t;
}
__device__ __forceinline__ float ex2(float x) {
    float y;
    asm("ex2.approx.ftz.f32 %0, %1;" : "=f"(y) : "f"(x));
    return y;
}

// ---------------------------------------------------------------------------
// Reductions
// ---------------------------------------------------------------------------
__device__ __forceinline__ float warpReduceSum(float v) {
    #pragma unroll
    for (int o = 16; o > 0; o >>= 1) v += __shfl_xor_sync(0xffffffffu, v, o);
    return v;
}

// ---------------------------------------------------------------------------
// Fused convert of all 6 weight matrices fp32 -> fp16, one launch.
// ---------------------------------------------------------------------------
#define CVT_Q (DD*DD/4)        // 262144 (= 2^18)
#define CVT_F (DFFN*DD/4)      // 1048576
#define CVT_TOTAL (4*CVT_Q + 2*CVT_F)   // 3145728

__global__ __launch_bounds__(256) void cvt_all(
    const float* __restrict__ wq, const float* __restrict__ wk,
    const float* __restrict__ wv, const float* __restrict__ wo,
    const float* __restrict__ w1, const float* __restrict__ w2,
    h16* __restrict__ oq, h16* __restrict__ ok, h16* __restrict__ ov,
    h16* __restrict__ oo, h16* __restrict__ o1, h16* __restrict__ o2)
{
    int i = blockIdx.x * 256 + threadIdx.x;
    if (i >= CVT_TOTAL) return;
    const float* src; h16* dst; int off;
    if (i < 4*CVT_Q) {
        int w = i >> 18; off = i & (CVT_Q - 1);
        src = (w==0) ? wq : (w==1) ? wk : (w==2) ? wv : wo;
        dst = (w==0) ? oq : (w==1) ? ok : (w==2) ? ov : oo;
    } else if (i < 4*CVT_Q + CVT_F) {
        src = w1; dst = o1; off = i - 4*CVT_Q;
    } else {
        src = w2; dst = o2; off = i - 4*CVT_Q - CVT_F;
    }
    float4 v = ((const float4*)src)[off];
    ((__half2*)dst)[off*2]   = __floats2half2_rn(v.x, v.y);
    ((__half2*)dst)[off*2+1] = __floats2half2_rn(v.z, v.w);
}

// ---------------------------------------------------------------------------
// LayerNorm -> fp16. One 256-thread block per row of 1024.
// torch semantics: alpha * (x - mean) / (sqrt(var_unbiased) + eps) + bias
// ---------------------------------------------------------------------------
__global__ __launch_bounds__(256) void layernorm_k(
    const float* __restrict__ x, const float* __restrict__ alpha,
    const float* __restrict__ beta, h16* __restrict__ oh)
{
    int row = blockIdx.x;
    const float* xr = x + (size_t)row * DD;
    int i = threadIdx.x * 4;
    float4 xv = *(const float4*)(xr + i);
    float s  = xv.x + xv.y + xv.z + xv.w;
    float s2 = xv.x*xv.x + xv.y*xv.y + xv.z*xv.z + xv.w*xv.w;

    __shared__ float rs[8], rs2[8];
    __shared__ float smean, sinv;
    s  = warpReduceSum(s);
    s2 = warpReduceSum(s2);
    int w = threadIdx.x >> 5, l = threadIdx.x & 31;
    if (l == 0) { rs[w] = s; rs2[w] = s2; }
    __syncthreads();
    if (threadIdx.x == 0) {
        float S = 0.f, S2 = 0.f;
        #pragma unroll
        for (int k = 0; k < 8; k++) { S += rs[k]; S2 += rs2[k]; }
        float mean = S * (1.0f / (float)DD);
        float var  = (S2 - (float)DD * mean * mean) * (1.0f / (float)(DD - 1));
        var = fmaxf(var, 0.0f);
        smean = mean;
        sinv  = 1.0f / (sqrtf(var) + LN_EPS);
    }
    __syncthreads();
    float m = smean, inv = sinv;
    float4 av = *(const float4*)(alpha + i);
    float4 bv = *(const float4*)(beta  + i);
    float o0 = av.x * (xv.x - m) * inv + bv.x;
    float o1 = av.y * (xv.y - m) * inv + bv.y;
    float o2 = av.z * (xv.z - m) * inv + bv.z;
    float o3 = av.w * (xv.w - m) * inv + bv.w;
    size_t off = (size_t)row * DD + i;
    ((__half2*)(oh + off))[0] = __floats2half2_rn(o0, o1);
    ((__half2*)(oh + off))[1] = __floats2half2_rn(o2, o3);
}

// ---------------------------------------------------------------------------
// GEMM tiling: 128x128 tile, BK=32, 256 threads (8 warps 4x2; 32x64/warp),
// single fp16 product, 3-stage cp.async pipeline, ONE sync per chunk.
// ---------------------------------------------------------------------------
#define BK 32
#define LDSX 40                       // padded row stride in h16 elems (80B)
#define MATB (128 * LDSX * 2)         // 10240 B per matrix tile
#define STAGE (2 * MATB)              // A, B
#define NSTG 3
#define GEMM_SMEM (NSTG * STAGE)      // 61440 B

__device__ __forceinline__ uint32_t a_ldsm_off(int lane) {
    int r = ((lane >> 3) & 1) * 8 + (lane & 7);
    int c = (lane >> 4) * 8;
    return (uint32_t)(r * LDSX + c) * 2;
}
__device__ __forceinline__ uint32_t b_ldsm_off(int lane) {
    int r = (lane >> 4) * 8 + (lane & 7);
    int c = ((lane >> 3) & 1) * 8;
    return (uint32_t)(r * LDSX + c) * 2;
}

template<bool BIAS, bool RELU, bool RES, bool OUTH>
__device__ __forceinline__ void gemm_body(
    const h16* __restrict__ A, const h16* __restrict__ B,
    const float* __restrict__ bias, const float* __restrict__ res,
    float* __restrict__ Cf, h16* __restrict__ Ch,
    int m0, int n0, int N, int K, uint32_t sbase)
{
    int tid = threadIdx.x, lane = tid & 31, wid = tid >> 5;
    int wm = wid & 3, wn = wid >> 2;
    int lr = lane >> 2, lk2 = (lane & 3) * 2;
    uint32_t aoff = a_ldsm_off(lane) + (uint32_t)(wm * 32) * (LDSX * 2);
    uint32_t boff = b_ldsm_off(lane) + (uint32_t)(wn * 64) * (LDSX * 2);

    float acc[2][8][4];
    #pragma unroll
    for (int a = 0; a < 2; a++)
        #pragma unroll
        for (int b = 0; b < 8; b++)
            #pragma unroll
            for (int c = 0; c < 4; c++) acc[a][b][c] = 0.f;

    const int NC = K / BK;

    auto load_chunk = [&](int c, int buf) {
        int kc = c * BK;
        uint32_t base = sbase + buf * STAGE;
        #pragma unroll
        for (int T = 0; T < 2; T++) {
            const h16* src = (T == 0) ? A : B;
            int r0 = (T == 0) ? m0 : n0;
            uint32_t mb = base + T * MATB;
            int row = tid >> 1, c16 = tid & 1;
            cp16(mb + row * (LDSX * 2) + c16 * 32,
                 src + (size_t)(r0 + row) * K + kc + c16 * 16);
            cp16(mb + row * (LDSX * 2) + c16 * 32 + 16,
                 src + (size_t)(r0 + row) * K + kc + c16 * 16 + 8);
        }
        cp_commit();
    };

    load_chunk(0, 0);
    load_chunk(1, 1);

    for (int c = 0; c < NC; c++) {
        if (c + 2 < NC) cp_wait<1>(); else cp_wait<0>();
        __syncthreads();
        if (c + 2 < NC) load_chunk(c + 2, (c + 2) % NSTG);

        uint32_t stg = sbase + (c % NSTG) * STAGE;
        uint32_t sA = stg + aoff;
        uint32_t sB = stg + MATB + boff;

        #pragma unroll
        for (int ks = 0; ks < 2; ks++) {
            uint32_t ah[2][4];
            #pragma unroll
            for (int mf = 0; mf < 2; mf++)
                ldsm4(ah[mf], sA + (uint32_t)(mf * 16) * (LDSX * 2) + ks * 32);
            #pragma unroll
            for (int nf2 = 0; nf2 < 4; nf2++) {
                uint32_t bh[4];
                ldsm4(bh, sB + (uint32_t)(nf2 * 16) * (LDSX * 2) + ks * 32);
                #pragma unroll
                for (int mf = 0; mf < 2; mf++) {
                    mma16816(acc[mf][2*nf2],     ah[mf], bh);
                    mma16816(acc[mf][2*nf2 + 1], ah[mf], bh + 2);
                }
            }
        }
    }

    // epilogue
    #pragma unroll
    for (int mf = 0; mf < 2; mf++) {
        int r0 = m0 + wm * 32 + mf * 16 + lr;
        #pragma unroll
        for (int nf = 0; nf < 8; nf++) {
            int col = n0 + wn * 64 + nf * 8 + lk2;
            float* cc = acc[mf][nf];
            float v00 = cc[0], v01 = cc[1], v10 = cc[2], v11 = cc[3];
            if (BIAS) {
                float b0 = __ldg(bias + col), b1 = __ldg(bias + col + 1);
                v00 += b0; v01 += b1; v10 += b0; v11 += b1;
            }
            if (RELU) {
                v00 = fmaxf(v00, 0.f); v01 = fmaxf(v01, 0.f);
                v10 = fmaxf(v10, 0.f); v11 = fmaxf(v11, 0.f);
            }
            if (RES) {
                float2 ra = *(const float2*)(res + (size_t)r0 * N + col);
                float2 rb = *(const float2*)(res + (size_t)(r0 + 8) * N + col);
                v00 += ra.x; v01 += ra.y; v10 += rb.x; v11 += rb.y;
            }
            if (OUTH) {
                *(__half2*)(Ch + (size_t)r0 * N + col)       = __floats2half2_rn(v00, v01);
                *(__half2*)(Ch + (size_t)(r0 + 8) * N + col) = __floats2half2_rn(v10, v11);
            } else {
                *(float2*)(Cf + (size_t)r0 * N + col)       = make_float2(v00, v01);
                *(float2*)(Cf + (size_t)(r0 + 8) * N + col) = make_float2(v10, v11);
            }
        }
    }
}

template<bool BIAS, bool RELU, bool RES, bool OUTH>
__global__ __launch_bounds__(256, 2) void gemm_h(
    const h16* __restrict__ A, const h16* __restrict__ B,
    const float* __restrict__ bias, const float* __restrict__ res,
    float* __restrict__ Cf, h16* __restrict__ Ch, int N, int K)
{
    extern __shared__ char sm_raw[];
    gemm_body<BIAS, RELU, RES, OUTH>(
        A, B, bias, res, Cf, Ch,
        blockIdx.y * 128, blockIdx.x * 128, N, K, smem_u32(sm_raw));
}

// Fused QKV: grid.x = 24; which = bx>>3 selects weight/output.
__global__ __launch_bounds__(256, 2) void gemm_qkv(
    const h16* __restrict__ A,
    const h16* __restrict__ B0, const h16* __restrict__ B1,
    const h16* __restrict__ B2,
    h16* __restrict__ C0, h16* __restrict__ C1, h16* __restrict__ C2)
{
    extern __shared__ char sm_raw[];
    int which = blockIdx.x >> 3;
    const h16* Bw = (which == 0) ? B0 : (which == 1) ? B1 : B2;
    h16* Cw = (which == 0) ? C0 : (which == 1) ? C1 : C2;
    gemm_body<false, false, false, true>(
        A, Bw, nullptr, nullptr, nullptr, Cw,
        blockIdx.y * 128, (blockIdx.x & 7) * 128, DD, DD, smem_u32(sm_raw));
}

// ---------------------------------------------------------------------------
// Flash attention (fp16 mma.sync): one CTA per (b, h, 128-query tile).
// 8 warps x 16 Q rows. K/V chunks of 64 keys, 3-stage cp.async pipeline.
// Base-2 online softmax: scale 1/8*log2e folded into Q at load; raw ex2;
// warp-uniform skip of the rescale when no row max changed.
// ---------------------------------------------------------------------------
#define AKST 72                       // smem row stride in h16 (144 B)
#define AKBUF (64 * AKST * 2)         // 9216 B per K (or V) stage
#define AVS_OFF (NSTG * AKBUF)        // 27648
#define AMSK_OFF (2 * NSTG * AKBUF)   // 55296
#define ATTN_SMEM (AMSK_OFF + NSTG * 64 * 4)   // 56064 B

#define QSCALE 0.18033688011112042f   // 0.125 * log2(e)

__global__ __launch_bounds__(256, 2) void fattn_k(
    const h16* __restrict__ qg, const h16* __restrict__ kg,
    const h16* __restrict__ vg, const int* __restrict__ mask,
    h16* __restrict__ avo)
{
    extern __shared__ char sm_raw[];
    uint32_t sbase = smem_u32(sm_raw);
    int* msk_s = (int*)(sm_raw + AMSK_OFF);

    int t = threadIdx.x, lane = t & 31, w = t >> 5;
    int h = blockIdx.y & (HH - 1), b = blockIdx.y >> 4;
    size_t base = (size_t)b * SS * DD + h * DKK;
    int q0 = blockIdx.x * 128 + w * 16;
    int lr = lane >> 2, q4 = lane & 3;
    int l7 = lane & 7, lg8 = (lane >> 3) & 1, lg16 = (lane >> 4) & 1;

    // Q fragments with 1/8*log2e folded in (base-2 softmax domain)
    const __half2 qs2 = __float2half2_rn(QSCALE);
    uint32_t qf[4][4];
    #pragma unroll
    for (int ks = 0; ks < 4; ks++) {
        int col = ks * 16 + q4 * 2;
        uint32_t r0 = *(const uint32_t*)(qg + base + (size_t)(q0 + lr) * DD + col);
        uint32_t r1 = *(const uint32_t*)(qg + base + (size_t)(q0 + lr + 8) * DD + col);
        uint32_t r2 = *(const uint32_t*)(qg + base + (size_t)(q0 + lr) * DD + col + 8);
        uint32_t r3 = *(const uint32_t*)(qg + base + (size_t)(q0 + lr + 8) * DD + col + 8);
        __half2 h0 = __hmul2(*(__half2*)&r0, qs2);
        __half2 h1 = __hmul2(*(__half2*)&r1, qs2);
        __half2 h2 = __hmul2(*(__half2*)&r2, qs2);
        __half2 h3 = __hmul2(*(__half2*)&r3, qs2);
        qf[ks][0] = *(uint32_t*)&h0;
        qf[ks][1] = *(uint32_t*)&h1;
        qf[ks][2] = *(uint32_t*)&h2;
        qf[ks][3] = *(uint32_t*)&h3;
    }

    float vacc[8][4];
    #pragma unroll
    for (int nf = 0; nf < 8; nf++)
        #pragma unroll
        for (int c = 0; c < 4; c++) vacc[nf][c] = 0.f;
    float m0 = -1e30f, m1 = -1e30f, l0 = 0.f, l1 = 0.f;

    const int NC = SS / 64;

    auto load_chunk = [&](int c, int buf) {
        int key0 = c * 64;
        uint32_t kbAddr = sbase + buf * AKBUF;
        uint32_t vbAddr = sbase + AVS_OFF + buf * AKBUF;
        #pragma unroll
        for (int i = 0; i < 2; i++) {
            int idx = t * 2 + i;
            int row = idx >> 3, seg = idx & 7;
            cp16(kbAddr + row * (AKST * 2) + seg * 16,
                 kg + base + (size_t)(key0 + row) * DD + seg * 8);
            cp16(vbAddr + row * (AKST * 2) + seg * 16,
                 vg + base + (size_t)(key0 + row) * DD + seg * 8);
        }
        if (t < 16)
            cp16(sbase + AMSK_OFF + buf * 256 + t * 16,
                 mask + b * SS + key0 + t * 4);
        cp_commit();
    };

    load_chunk(0, 0);
    load_chunk(1, 1);

    for (int c = 0; c < NC; c++) {
        if (c + 2 < NC) cp_wait<1>(); else cp_wait<0>();
        __syncthreads();
        if (c + 2 < NC) load_chunk(c + 2, (c + 2) % NSTG);
        int buf = c % NSTG;

        float sacc[8][4];
        #pragma unroll
        for (int nf = 0; nf < 8; nf++)
            #pragma unroll
            for (int cc = 0; cc < 4; cc++) sacc[nf][cc] = 0.f;

        uint32_t ksb = sbase + buf * AKBUF;
        #pragma unroll
        for (int ks = 0; ks < 4; ks++) {
            #pragma unroll
            for (int nfp = 0; nfp < 4; nfp++) {
                uint32_t kf[4];
                uint32_t addr = ksb
                    + (uint32_t)(nfp * 16 + lg16 * 8 + l7) * (AKST * 2)
                    + ks * 32 + lg8 * 16;
                ldsm4(kf, addr);
                mma16816(sacc[2*nfp],     qf[ks], kf);
                mma16816(sacc[2*nfp + 1], qf[ks], kf + 2);
            }
        }

        // mask (scores already scaled via Q); masked -> very negative
        #pragma unroll
        for (int nf = 0; nf < 8; nf++) {
            int col = nf * 8 + q4 * 2;
            int mk0 = msk_s[buf * 64 + col], mk1 = msk_s[buf * 64 + col + 1];
            if (!mk0) { sacc[nf][0] = -3e8f; sacc[nf][2] = -3e8f; }
            if (!mk1) { sacc[nf][1] = -3e8f; sacc[nf][3] = -3e8f; }
        }

        // chunk max
        float cm0 = -1e30f, cm1 = -1e30f;
        #pragma unroll
        for (int nf = 0; nf < 8; nf++) {
            cm0 = fmaxf(cm0, fmaxf(sacc[nf][0], sacc[nf][1]));
            cm1 = fmaxf(cm1, fmaxf(sacc[nf][2], sacc[nf][3]));
        }
        cm0 = fmaxf(cm0, __shfl_xor_sync(0xffffffffu, cm0, 1));
        cm0 = fmaxf(cm0, __shfl_xor_sync(0xffffffffu, cm0, 2));
        cm1 = fmaxf(cm1, __shfl_xor_sync(0xffffffffu, cm1, 1));
        cm1 = fmaxf(cm1, __shfl_xor_sync(0xffffffffu, cm1, 2));
        float nm0 = fmaxf(m0, cm0), nm1 = fmaxf(m1, cm1);

        // warp-uniform rescale skip: only rescale when some row max changed
        bool stable = (nm0 == m0) && (nm1 == m1);
        if (!__all_sync(0xffffffffu, stable)) {
            float sc0 = ex2(m0 - nm0), sc1 = ex2(m1 - nm1);
            l0 *= sc0; l1 *= sc1;
            #pragma unroll
            for (int nf = 0; nf < 8; nf++) {
                vacc[nf][0] *= sc0; vacc[nf][1] *= sc0;
                vacc[nf][2] *= sc1; vacc[nf][3] *= sc1;
            }
            m0 = nm0; m1 = nm1;
        }

        // p = 2^(s - m), accumulate row sums
        #pragma unroll
        for (int nf = 0; nf < 8; nf++) {
            float p0 = ex2(sacc[nf][0] - m0);
            float p1 = ex2(sacc[nf][1] - m0);
            float p2 = ex2(sacc[nf][2] - m1);
            float p3 = ex2(sacc[nf][3] - m1);
            sacc[nf][0] = p0; sacc[nf][1] = p1;
            sacc[nf][2] = p2; sacc[nf][3] = p3;
            l0 += p0 + p1; l1 += p2 + p3;
        }

        uint32_t pf[4][4];
        #pragma unroll
        for (int ks = 0; ks < 4; ks++) {
            pf[ks][0] = packh(sacc[2*ks][0],     sacc[2*ks][1]);
            pf[ks][1] = packh(sacc[2*ks][2],     sacc[2*ks][3]);
            pf[ks][2] = packh(sacc[2*ks + 1][0], sacc[2*ks + 1][1]);
            pf[ks][3] = packh(sacc[2*ks + 1][2], sacc[2*ks + 1][3]);
        }

        uint32_t vsb = sbase + AVS_OFF + buf * AKBUF;
        #pragma unroll
        for (int nfp = 0; nfp < 4; nfp++) {
            #pragma unroll
            for (int ks = 0; ks < 4; ks++) {
                uint32_t vf[4];
                uint32_t addr = vsb
                    + (uint32_t)(ks * 16 + lg8 * 8 + l7) * (AKST * 2)
                    + nfp * 32 + lg16 * 16;
                ldsm4t(vf, addr);
                mma16816(vacc[2*nfp],     pf[ks], vf);
                mma16816(vacc[2*nfp + 1], pf[ks], vf + 2);
            }
        }
    }

    l0 += __shfl_xor_sync(0xffffffffu, l0, 1);
    l0 += __shfl_xor_sync(0xffffffffu, l0, 2);
    l1 += __shfl_xor_sync(0xffffffffu, l1, 1);
    l1 += __shfl_xor_sync(0xffffffffu, l1, 2);
    float r0 = 1.0f / l0, r1 = 1.0f / l1;

    #pragma unroll
    for (int nf = 0; nf < 8; nf++) {
        int col = nf * 8 + q4 * 2;
        size_t o0 = base + (size_t)(q0 + lr) * DD + col;
        size_t o1 = base + (size_t)(q0 + lr + 8) * DD + col;
        *(__half2*)(avo + o0) = __floats2half2_rn(vacc[nf][0] * r0, vacc[nf][1] * r0);
        *(__half2*)(avo + o1) = __floats2half2_rn(vacc[nf][2] * r1, vacc[nf][3] * r1);
    }
}

// ---------------------------------------------------------------------------
// Driver
// ---------------------------------------------------------------------------
extern "C" void kernel_launch(void* const* d_in, const int* in_sizes, int n_in,
                              void* d_out, int out_size)
{
    const float* x      = (const float*)d_in[0];
    const int*   mask   = (const int*)  d_in[1];
    const float* wq     = (const float*)d_in[2];
    const float* wk     = (const float*)d_in[3];
    const float* wv     = (const float*)d_in[4];
    const float* wo     = (const float*)d_in[5];
    const float* w1     = (const float*)d_in[6];
    const float* b1     = (const float*)d_in[7];
    const float* w2     = (const float*)d_in[8];
    const float* b2     = (const float*)d_in[9];
    const float* alpha1 = (const float*)d_in[10];
    const float* bias1  = (const float*)d_in[11];
    const float* alpha2 = (const float*)d_in[12];
    const float* bias2  = (const float*)d_in[13];
    float* out = (float*)d_out;

    h16 *xn, *qb, *kb, *vb, *av, *xn2, *hb;
    h16 *wqh, *wkh, *wvh, *woh, *w1h, *w2h;
    float *x1;
    cudaGetSymbolAddress((void**)&xn,   g_xn);
    cudaGetSymbolAddress((void**)&qb,   g_qb);   cudaGetSymbolAddress((void**)&kb,   g_kb);
    cudaGetSymbolAddress((void**)&vb,   g_vb);
    cudaGetSymbolAddress((void**)&av,   g_av);
    cudaGetSymbolAddress((void**)&x1,   g_x1);
    cudaGetSymbolAddress((void**)&xn2,  g_xn2);
    cudaGetSymbolAddress((void**)&hb,   g_hb);
    cudaGetSymbolAddress((void**)&wqh,  g_wqh);
    cudaGetSymbolAddress((void**)&wkh,  g_wkh);
    cudaGetSymbolAddress((void**)&wvh,  g_wvh);
    cudaGetSymbolAddress((void**)&woh,  g_woh);
    cudaGetSymbolAddress((void**)&w1h,  g_w1h);
    cudaGetSymbolAddress((void**)&w2h,  g_w2h);

    cudaFuncSetAttribute(gemm_h<false,false,true,false>,
                         cudaFuncAttributeMaxDynamicSharedMemorySize, GEMM_SMEM);
    cudaFuncSetAttribute(gemm_h<true,true,false,true>,
                         cudaFuncAttributeMaxDynamicSharedMemorySize, GEMM_SMEM);
    cudaFuncSetAttribute(gemm_h<true,false,true,false>,
                         cudaFuncAttributeMaxDynamicSharedMemorySize, GEMM_SMEM);
    cudaFuncSetAttribute(gemm_qkv,
                         cudaFuncAttributeMaxDynamicSharedMemorySize, GEMM_SMEM);
    cudaFuncSetAttribute(fattn_k,
                         cudaFuncAttributeMaxDynamicSharedMemorySize, ATTN_SMEM);

    // 0. all weights -> fp16, single launch
    cvt_all<<<(CVT_TOTAL + 255)/256, 256>>>(
        wq, wk, wv, wo, w1, w2, wqh, wkh, wvh, woh, w1h, w2h);

    // 1. LN1 -> fp16
    layernorm_k<<<NTOK, 256>>>(x, alpha1, bias1, xn);

    // 2. fused Q/K/V projections (fp16)
    dim3 gQKV(3 * (DD / 128), NTOK / 128);  // (24, 32)
    gemm_qkv<<<gQKV, 256, GEMM_SMEM>>>(xn, wqh, wkh, wvh, qb, kb, vb);

    // 3. flash attention -> fp16
    dim3 gAttn(SS / 128, BB * HH);          // (16, 32)
    fattn_k<<<gAttn, 256, ATTN_SMEM>>>(qb, kb, vb, mask, av);

    // 4. output projection + residual(x) -> x1 fp32
    dim3 gProj(DD / 128, NTOK / 128);       // (8, 32)
    gemm_h<false,false,true,false><<<gProj, 256, GEMM_SMEM>>>(
        av, woh, nullptr, x, x1, nullptr, DD, DD);

    // 5. LN2 -> fp16
    layernorm_k<<<NTOK, 256>>>(x1, alpha2, bias2, xn2);

    // 6. FFN up: relu(xn2@w1^T + b1) -> fp16
    dim3 gF1(DFFN / 128, NTOK / 128);       // (32, 32)
    gemm_h<true,true,false,true><<<gF1, 256, GEMM_SMEM>>>(
        xn2, w1h, b1, nullptr, nullptr, hb, DFFN, DD);

    // 7. FFN down: h@w2^T + b2 + x1 -> out fp32
    gemm_h<true,false,true,false><<<gProj, 256, GEMM_SMEM>>>(
        hb, w2h, b2, x1, out, nullptr, DD, DFFN);
}